// round 1
// baseline (speedup 1.0000x reference)
#include <cuda_runtime.h>
#include <math.h>
#include <stdint.h>

// ---------------- problem constants ----------------
#define BATCH 16
#define CCH   512          // C and Dq and Dv
#define HW    4096         // H*W
#define DHID  2048         // Dh
#define NHEAD 8
#define HDIM  64           // Dq/NHEAD
#define PERB  (CCH*HW)     // 2^21 elements per batch for LN
#define LN_EPS 1e-5f

// ---------------- device scratch (allocation-free) ----------------
__device__ float g_A [BATCH*CCH*HW];   // ln1 out, later attn output
__device__ float g_Q [BATCH*CCH*HW];   // Q, later residual R = x + hu(attn)
__device__ float g_K [BATCH*CCH*HW];
__device__ float g_V [BATCH*CCH*HW];
__device__ float g_F [BATCH*DHID*HW];  // ff1/gelu output
__device__ float g_KV[BATCH*NHEAD*HDIM*HDIM];
__device__ float2 g_part[BATCH*128];
__device__ float2 g_stats[BATCH];

// ---------------- block reductions (256 threads) ----------------
__device__ __forceinline__ float bred_sum(float v) {
    __shared__ float sb[8];
    int lane = threadIdx.x & 31, w = threadIdx.x >> 5;
    #pragma unroll
    for (int o = 16; o; o >>= 1) v += __shfl_down_sync(0xffffffffu, v, o);
    if (lane == 0) sb[w] = v;
    __syncthreads();
    if (threadIdx.x < 32) {
        float r = (lane < 8) ? sb[lane] : 0.f;
        #pragma unroll
        for (int o = 4; o; o >>= 1) r += __shfl_down_sync(0xffffffffu, r, o);
        if (lane == 0) sb[0] = r;
    }
    __syncthreads();
    float out = sb[0];
    __syncthreads();
    return out;
}

__device__ __forceinline__ float bred_max(float v) {
    __shared__ float sb[8];
    int lane = threadIdx.x & 31, w = threadIdx.x >> 5;
    #pragma unroll
    for (int o = 16; o; o >>= 1) v = fmaxf(v, __shfl_down_sync(0xffffffffu, v, o));
    if (lane == 0) sb[w] = v;
    __syncthreads();
    if (threadIdx.x < 32) {
        float r = (lane < 8) ? sb[lane] : -1e30f;
        #pragma unroll
        for (int o = 4; o; o >>= 1) r = fmaxf(r, __shfl_down_sync(0xffffffffu, r, o));
        if (lane == 0) sb[0] = r;
    }
    __syncthreads();
    float out = sb[0];
    __syncthreads();
    return out;
}

// ---------------- LayerNorm over (C,H,W) per batch ----------------
// stage 1: per-block partial sum/sumsq. grid = (128, BATCH), 256 thr, 16384 elems/block
__global__ __launch_bounds__(256) void ln_stats(const float* __restrict__ in,
                                                float2* __restrict__ part) {
    int b = blockIdx.y, pb = blockIdx.x;
    const float* p = in + (size_t)b * PERB + (size_t)pb * 16384;
    float s = 0.f, q = 0.f;
    #pragma unroll
    for (int i = 0; i < 16; i++) {
        float4 v = *reinterpret_cast<const float4*>(p + (size_t)(threadIdx.x + i * 256) * 4);
        s += v.x + v.y + v.z + v.w;
        q += v.x * v.x + v.y * v.y + v.z * v.z + v.w * v.w;
    }
    s = bred_sum(s);
    q = bred_sum(q);
    if (threadIdx.x == 0) part[b * 128 + pb] = make_float2(s, q);
}

// stage 2: deterministic final reduce per batch
__global__ void ln_finalize(const float2* __restrict__ part, float2* __restrict__ stats) {
    int t = threadIdx.x;
    if (t < BATCH) {
        double s = 0.0, q = 0.0;
        for (int i = 0; i < 128; i++) {
            float2 p = part[t * 128 + i];
            s += (double)p.x; q += (double)p.y;
        }
        double invN = 1.0 / (double)PERB;
        double mu = s * invN;
        double var = q * invN - mu * mu;
        double rstd = 1.0 / sqrt(var + (double)LN_EPS);
        stats[t] = make_float2((float)mu, (float)rstd);
    }
}

// stage 3: apply. grid = 32768, 256 thr (float4 per thread)
__global__ __launch_bounds__(256) void ln_apply(const float* __restrict__ in,
                                                const float* __restrict__ w,
                                                const float* __restrict__ bsh,
                                                const float2* __restrict__ stats,
                                                float* __restrict__ out) {
    size_t i4 = (size_t)blockIdx.x * 256 + threadIdx.x;
    size_t idx = i4 * 4;
    int b = (int)(idx >> 21);
    size_t j = idx & (size_t)(PERB - 1);
    float2 st = stats[b];
    float4 xv = *reinterpret_cast<const float4*>(in + idx);
    float4 wv = *reinterpret_cast<const float4*>(w + j);
    float4 bv = *reinterpret_cast<const float4*>(bsh + j);
    float4 o;
    o.x = (xv.x - st.x) * st.y * wv.x + bv.x;
    o.y = (xv.y - st.x) * st.y * wv.y + bv.y;
    o.z = (xv.z - st.x) * st.y * wv.z + bv.z;
    o.w = (xv.w - st.x) * st.y * wv.w + bv.w;
    *reinterpret_cast<float4*>(out + idx) = o;
}

// ---------------- tiled SGEMM: Out[b] = Wt(MxK) @ In[b](KxN) + bias, epilogues ----------------
// EPI 0: +bias   1: +bias + aux[b] (residual)   2: gelu(+bias) exact   3: +bias, accumulate into Out
template <int EPI>
__global__ __launch_bounds__(256) void sgemm(const float* __restrict__ Wt,
                                             const float* __restrict__ In,
                                             const float* __restrict__ bias,
                                             const float* __restrict__ aux,
                                             float* __restrict__ Out,
                                             int M, int N, int K) {
    constexpr int BM = 128, BN = 128, BK = 16, TM = 8, TN = 8;
    __shared__ float As[BK][BM];
    __shared__ float Bs[BK][BN];
    const int b = blockIdx.z;
    const float* Bb = In + (size_t)b * K * N;
    const int m0 = blockIdx.y * BM, n0 = blockIdx.x * BN;
    const int tid = threadIdx.x;
    const int tx = tid & 15, ty = tid >> 4;

    const int a_row  = tid >> 2;
    const int a_col4 = (tid & 3) * 4;
    const int b_row  = tid >> 5;
    const int b_col4 = (tid & 31) * 4;

    float acc[TM][TN];
    #pragma unroll
    for (int i = 0; i < TM; i++)
        #pragma unroll
        for (int j = 0; j < TN; j++) acc[i][j] = 0.f;

    for (int k0 = 0; k0 < K; k0 += BK) {
        #pragma unroll
        for (int i = 0; i < 2; i++) {
            int r = a_row + i * 64;
            float4 v = *reinterpret_cast<const float4*>(&Wt[(size_t)(m0 + r) * K + k0 + a_col4]);
            As[a_col4 + 0][r] = v.x; As[a_col4 + 1][r] = v.y;
            As[a_col4 + 2][r] = v.z; As[a_col4 + 3][r] = v.w;
        }
        #pragma unroll
        for (int i = 0; i < 2; i++) {
            int r = b_row + i * 8;
            *reinterpret_cast<float4*>(&Bs[r][b_col4]) =
                *reinterpret_cast<const float4*>(&Bb[(size_t)(k0 + r) * N + n0 + b_col4]);
        }
        __syncthreads();
        #pragma unroll
        for (int k = 0; k < BK; k++) {
            float4 a0 = *reinterpret_cast<const float4*>(&As[k][ty * TM]);
            float4 a1 = *reinterpret_cast<const float4*>(&As[k][ty * TM + 4]);
            float4 b0 = *reinterpret_cast<const float4*>(&Bs[k][tx * TN]);
            float4 b1 = *reinterpret_cast<const float4*>(&Bs[k][tx * TN + 4]);
            float ra[TM] = {a0.x, a0.y, a0.z, a0.w, a1.x, a1.y, a1.z, a1.w};
            float rb[TN] = {b0.x, b0.y, b0.z, b0.w, b1.x, b1.y, b1.z, b1.w};
            #pragma unroll
            for (int i = 0; i < TM; i++)
                #pragma unroll
                for (int j = 0; j < TN; j++)
                    acc[i][j] = fmaf(ra[i], rb[j], acc[i][j]);
        }
        __syncthreads();
    }

    size_t outbase = (size_t)b * M * N;
    #pragma unroll
    for (int i = 0; i < TM; i++) {
        int m = m0 + ty * TM + i;
        float bv = bias[m];
        #pragma unroll
        for (int j = 0; j < TN; j++) {
            int n = n0 + tx * TN + j;
            size_t idx = outbase + (size_t)m * N + n;
            float v = acc[i][j] + bv;
            if (EPI == 1) v += aux[idx];
            else if (EPI == 2) v = 0.5f * v * (1.0f + erff(v * 0.70710678118654752f));
            else if (EPI == 3) v += Out[idx];
            Out[idx] = v;
        }
    }
}

// ---------------- softmax over channels (axis=1), per pixel, in place ----------------
__global__ __launch_bounds__(256) void softmax_ch(float* __restrict__ Q) {
    int gid = blockIdx.x * 256 + threadIdx.x;        // 0..65535
    int b = gid >> 12, pix = gid & 4095;
    float* base = Q + (size_t)b * PERB + pix;
    float m = -1e30f, s = 0.f;
    for (int c = 0; c < CCH; c++) {
        float v = base[(size_t)c * HW];
        if (v > m) { s = s * expf(m - v) + 1.f; m = v; }
        else       { s += expf(v - m); }
    }
    float inv = 1.f / s;
    for (int c = 0; c < CCH; c++) {
        float v = base[(size_t)c * HW];
        base[(size_t)c * HW] = expf(v - m) * inv;
    }
}

// ---------------- softmax over spatial dim, per (b,channel) row, in place ----------------
__global__ __launch_bounds__(256) void softmax_sp(float* __restrict__ Kp) {
    float* row = Kp + (size_t)blockIdx.x * HW;
    float4 v[4];
    float m = -1e30f;
    #pragma unroll
    for (int i = 0; i < 4; i++) {
        v[i] = reinterpret_cast<float4*>(row)[threadIdx.x + i * 256];
        m = fmaxf(m, fmaxf(fmaxf(v[i].x, v[i].y), fmaxf(v[i].z, v[i].w)));
    }
    m = bred_max(m);
    float s = 0.f;
    #pragma unroll
    for (int i = 0; i < 4; i++) {
        v[i].x = expf(v[i].x - m); v[i].y = expf(v[i].y - m);
        v[i].z = expf(v[i].z - m); v[i].w = expf(v[i].w - m);
        s += v[i].x + v[i].y + v[i].z + v[i].w;
    }
    s = bred_sum(s);
    float inv = 1.f / s;
    #pragma unroll
    for (int i = 0; i < 4; i++) {
        v[i].x *= inv; v[i].y *= inv; v[i].z *= inv; v[i].w *= inv;
        reinterpret_cast<float4*>(row)[threadIdx.x + i * 256] = v[i];
    }
}

// ---------------- KV[b,h] = K[b,h] (64 x 4096) @ V[b,h]^T -> (64 x 64) ----------------
__global__ __launch_bounds__(256) void kv_kernel(const float* __restrict__ Kp,
                                                 const float* __restrict__ Vp,
                                                 float* __restrict__ KV) {
    const int bh = blockIdx.x;   // b*8 + h ; head rows are contiguous in (B,512,HW)
    const float* Kb = Kp + (size_t)bh * HDIM * HW;
    const float* Vb = Vp + (size_t)bh * HDIM * HW;
    __shared__ float Ks[64][65];
    __shared__ float Vs[64][65];
    const int tid = threadIdx.x;
    const int tx = tid & 15, ty = tid >> 4;
    float acc[4][4] = {};
    for (int p0 = 0; p0 < HW; p0 += 64) {
        #pragma unroll
        for (int t = 0; t < 4; t++) {
            int lin = tid + t * 256;          // 0..1023 float4 slots
            int r = lin >> 4, c4 = (lin & 15) * 4;
            float4 kv4 = *reinterpret_cast<const float4*>(&Kb[(size_t)r * HW + p0 + c4]);
            float4 vv4 = *reinterpret_cast<const float4*>(&Vb[(size_t)r * HW + p0 + c4]);
            Ks[r][c4 + 0] = kv4.x; Ks[r][c4 + 1] = kv4.y; Ks[r][c4 + 2] = kv4.z; Ks[r][c4 + 3] = kv4.w;
            Vs[r][c4 + 0] = vv4.x; Vs[r][c4 + 1] = vv4.y; Vs[r][c4 + 2] = vv4.z; Vs[r][c4 + 3] = vv4.w;
        }
        __syncthreads();
        #pragma unroll 8
        for (int p = 0; p < 64; p++) {
            float ra[4], rb[4];
            #pragma unroll
            for (int i = 0; i < 4; i++) ra[i] = Ks[ty * 4 + i][p];
            #pragma unroll
            for (int j = 0; j < 4; j++) rb[j] = Vs[tx * 4 + j][p];
            #pragma unroll
            for (int i = 0; i < 4; i++)
                #pragma unroll
                for (int j = 0; j < 4; j++)
                    acc[i][j] = fmaf(ra[i], rb[j], acc[i][j]);
        }
        __syncthreads();
    }
    float* out = KV + (size_t)bh * HDIM * HDIM;
    #pragma unroll
    for (int i = 0; i < 4; i++)
        #pragma unroll
        for (int j = 0; j < 4; j++)
            out[(ty * 4 + i) * HDIM + tx * 4 + j] = acc[i][j];   // KV[k][v]
}

// ---------------- attn[b,h,v,p] = sum_k KV[b,h,k,v] * Q[b,h,k,p] ----------------
// grid (HW/64, B*NHEAD), 256 thr; p-tile 64
__global__ __launch_bounds__(256) void attn_kernel(const float* __restrict__ KV,
                                                   const float* __restrict__ Qp,
                                                   float* __restrict__ Out) {
    const int bh = blockIdx.y;
    const int p0 = blockIdx.x * 64;
    const float* Qb  = Qp + (size_t)bh * HDIM * HW;
    const float* KVb = KV + (size_t)bh * HDIM * HDIM;
    __shared__ float KVs[64][64];
    __shared__ float Qs[64][68];
    const int tid = threadIdx.x;
    const int tx = tid & 15, ty = tid >> 4;
    #pragma unroll
    for (int t = 0; t < 4; t++) {
        int lin = tid + t * 256;              // 1024 float4 slots = 4096 floats
        int r = lin >> 4, c4 = (lin & 15) * 4;
        *reinterpret_cast<float4*>(&KVs[r][c4]) =
            *reinterpret_cast<const float4*>(&KVb[(size_t)r * HDIM + c4]);
        float4 q4 = *reinterpret_cast<const float4*>(&Qb[(size_t)r * HW + p0 + c4]);
        *reinterpret_cast<float4*>(&Qs[r][c4]) = q4;
    }
    __syncthreads();
    float acc[4][4] = {};
    #pragma unroll 8
    for (int k = 0; k < 64; k++) {
        float4 q4 = *reinterpret_cast<const float4*>(&Qs[k][tx * 4]);
        float4 a4 = *reinterpret_cast<const float4*>(&KVs[k][ty * 4]);
        float ra[4] = {a4.x, a4.y, a4.z, a4.w};
        float rb[4] = {q4.x, q4.y, q4.z, q4.w};
        #pragma unroll
        for (int i = 0; i < 4; i++)
            #pragma unroll
            for (int j = 0; j < 4; j++)
                acc[i][j] = fmaf(ra[i], rb[j], acc[i][j]);
    }
    float* ob = Out + (size_t)bh * HDIM * HW;
    #pragma unroll
    for (int i = 0; i < 4; i++) {
        int v = ty * 4 + i;
        #pragma unroll
        for (int j = 0; j < 4; j++)
            ob[(size_t)v * HW + p0 + tx * 4 + j] = acc[i][j];
    }
}

// ---------------- launch ----------------
extern "C" void kernel_launch(void* const* d_in, const int* in_sizes, int n_in,
                              void* d_out, int out_size) {
    const float* x     = (const float*)d_in[0];
    const float* ln1w  = (const float*)d_in[1];
    const float* ln1b  = (const float*)d_in[2];
    const float* qw    = (const float*)d_in[3];
    const float* qb    = (const float*)d_in[4];
    const float* kw    = (const float*)d_in[5];
    const float* kb    = (const float*)d_in[6];
    const float* vw    = (const float*)d_in[7];
    const float* vb    = (const float*)d_in[8];
    const float* huw   = (const float*)d_in[9];
    const float* hub   = (const float*)d_in[10];
    const float* ln2w  = (const float*)d_in[11];
    const float* ln2b  = (const float*)d_in[12];
    const float* ff1w  = (const float*)d_in[13];
    const float* ff1b  = (const float*)d_in[14];
    const float* ff2w  = (const float*)d_in[15];
    const float* ff2b  = (const float*)d_in[16];
    float* out = (float*)d_out;

    float *A, *Q, *K, *V, *F, *KV;
    float2 *part, *stats;
    cudaGetSymbolAddress((void**)&A, g_A);
    cudaGetSymbolAddress((void**)&Q, g_Q);
    cudaGetSymbolAddress((void**)&K, g_K);
    cudaGetSymbolAddress((void**)&V, g_V);
    cudaGetSymbolAddress((void**)&F, g_F);
    cudaGetSymbolAddress((void**)&KV, g_KV);
    cudaGetSymbolAddress((void**)&part, g_part);
    cudaGetSymbolAddress((void**)&stats, g_stats);

    const dim3 gQKV(HW / 128, CCH / 128, BATCH);   // (32, 4, 16)
    const dim3 gFF1(HW / 128, DHID / 128, BATCH);  // (32, 16, 16)

    // a = ln1(x)
    ln_stats<<<dim3(128, BATCH), 256>>>(x, part);
    ln_finalize<<<1, 32>>>(part, stats);
    ln_apply<<<(BATCH * PERB) / 1024, 256>>>(x, ln1w, ln1b, stats, A);

    // Q, K, V
    sgemm<0><<<gQKV, 256>>>(qw, A, qb, nullptr, Q, CCH, HW, CCH);
    sgemm<0><<<gQKV, 256>>>(kw, A, kb, nullptr, K, CCH, HW, CCH);
    sgemm<0><<<gQKV, 256>>>(vw, A, vb, nullptr, V, CCH, HW, CCH);

    softmax_ch<<<(BATCH * HW) / 256, 256>>>(Q);
    softmax_sp<<<BATCH * CCH, 256>>>(K);

    kv_kernel<<<BATCH * NHEAD, 256>>>(K, V, KV);
    attn_kernel<<<dim3(HW / 64, BATCH * NHEAD), 256>>>(KV, Q, A);   // A = attn heads out

    // R = x + hu(attn) -> reuse Q buffer
    sgemm<1><<<gQKV, 256>>>(huw, A, hub, x, Q, CCH, HW, CCH);

    // y = ln2(R) -> d_out
    ln_stats<<<dim3(128, BATCH), 256>>>(Q, part);
    ln_finalize<<<1, 32>>>(part, stats);
    ln_apply<<<(BATCH * PERB) / 1024, 256>>>(Q, ln2w, ln2b, stats, out);

    // F = gelu(ff1(y)); out += ff2(F)
    sgemm<2><<<gFF1, 256>>>(ff1w, out, ff1b, nullptr, F, DHID, HW, CCH);
    sgemm<3><<<gQKV, 256>>>(ff2w, F, ff2b, nullptr, out, CCH, HW, DHID);
}

// round 4
// speedup vs baseline: 1.9142x; 1.9142x over previous
#include <cuda_runtime.h>
#include <cuda_bf16.h>
#include <math.h>
#include <stdint.h>

// ---------------- problem constants ----------------
#define BATCH 16
#define CCH   512
#define HW    4096
#define DHID  2048
#define NHEAD 8
#define HDIM  64
#define PERB  (CCH*HW)
#define LN_EPS 1e-5f

// ---------------- device scratch (allocation-free) ----------------
__device__ float g_A [BATCH*CCH*HW];
__device__ float g_Q [BATCH*CCH*HW];
__device__ float g_K [BATCH*CCH*HW];
__device__ float g_V [BATCH*CCH*HW];
__device__ float g_F [BATCH*DHID*HW];
__device__ float g_KV[BATCH*NHEAD*HDIM*HDIM];
__device__ float2 g_part[BATCH*128];
__device__ float2 g_stats[BATCH];
// bf16 hi/lo activations, pixel-major (b, p, c); sized for C up to 2048
__device__ __nv_bfloat16 g_Th[(size_t)BATCH*HW*DHID];
__device__ __nv_bfloat16 g_Tl[(size_t)BATCH*HW*DHID];
// bf16 hi/lo weights
#define WOFF_Q   0
#define WOFF_K   262144
#define WOFF_V   524288
#define WOFF_HU  786432
#define WOFF_FF1 1048576
#define WOFF_FF2 2097152
#define WTOT     3145728
__device__ __nv_bfloat16 g_Wh[WTOT];
__device__ __nv_bfloat16 g_Wl[WTOT];

// ================= PTX helpers (compute_103-safe: sm_80-era features only) =================
__device__ __forceinline__ uint32_t smem_u32(const void* p) {
    uint32_t a;
    asm("{ .reg .u64 t; cvta.to.shared.u64 t, %1; cvt.u32.u64 %0, t; }" : "=r"(a) : "l"(p));
    return a;
}
__device__ __forceinline__ void cp16(uint32_t dst, const void* src) {
    asm volatile("cp.async.cg.shared.global [%0], [%1], 16;" :: "r"(dst), "l"(src));
}
__device__ __forceinline__ void cp_commit() {
    asm volatile("cp.async.commit_group;" ::: "memory");
}
template <int N>
__device__ __forceinline__ void cp_wait() {
    asm volatile("cp.async.wait_group %0;" :: "n"(N) : "memory");
}
__device__ __forceinline__ void ldm_x4(uint32_t* r, uint32_t addr) {
    asm volatile("ldmatrix.sync.aligned.m8n8.x4.shared.b16 {%0,%1,%2,%3}, [%4];"
                 : "=r"(r[0]), "=r"(r[1]), "=r"(r[2]), "=r"(r[3]) : "r"(addr));
}
__device__ __forceinline__ void mma_bf16(float* c, const uint32_t* a, const uint32_t* b) {
    asm("mma.sync.aligned.m16n8k16.row.col.f32.bf16.bf16.f32 "
        "{%0,%1,%2,%3}, {%4,%5,%6,%7}, {%8,%9}, {%0,%1,%2,%3};"
        : "+f"(c[0]), "+f"(c[1]), "+f"(c[2]), "+f"(c[3])
        : "r"(a[0]), "r"(a[1]), "r"(a[2]), "r"(a[3]), "r"(b[0]), "r"(b[1]));
}

// ================= block reductions =================
__device__ __forceinline__ float bred_sum(float v) {
    __shared__ float sb[8];
    int lane = threadIdx.x & 31, w = threadIdx.x >> 5;
    #pragma unroll
    for (int o = 16; o; o >>= 1) v += __shfl_down_sync(0xffffffffu, v, o);
    if (lane == 0) sb[w] = v;
    __syncthreads();
    if (threadIdx.x < 32) {
        float r = (lane < 8) ? sb[lane] : 0.f;
        #pragma unroll
        for (int o = 4; o; o >>= 1) r += __shfl_down_sync(0xffffffffu, r, o);
        if (lane == 0) sb[0] = r;
    }
    __syncthreads();
    float out = sb[0];
    __syncthreads();
    return out;
}
__device__ __forceinline__ float bred_max(float v) {
    __shared__ float sb[8];
    int lane = threadIdx.x & 31, w = threadIdx.x >> 5;
    #pragma unroll
    for (int o = 16; o; o >>= 1) v = fmaxf(v, __shfl_down_sync(0xffffffffu, v, o));
    if (lane == 0) sb[w] = v;
    __syncthreads();
    if (threadIdx.x < 32) {
        float r = (lane < 8) ? sb[lane] : -1e30f;
        #pragma unroll
        for (int o = 4; o; o >>= 1) r = fmaxf(r, __shfl_down_sync(0xffffffffu, r, o));
        if (lane == 0) sb[0] = r;
    }
    __syncthreads();
    float out = sb[0];
    __syncthreads();
    return out;
}

// ================= LayerNorm =================
__global__ __launch_bounds__(256) void ln_stats(const float* __restrict__ in,
                                                float2* __restrict__ part) {
    int b = blockIdx.y, pb = blockIdx.x;
    const float* p = in + (size_t)b * PERB + (size_t)pb * 16384;
    float s = 0.f, q = 0.f;
    #pragma unroll
    for (int i = 0; i < 16; i++) {
        float4 v = *reinterpret_cast<const float4*>(p + (size_t)(threadIdx.x + i * 256) * 4);
        s += v.x + v.y + v.z + v.w;
        q += v.x * v.x + v.y * v.y + v.z * v.z + v.w * v.w;
    }
    s = bred_sum(s);
    q = bred_sum(q);
    if (threadIdx.x == 0) part[b * 128 + pb] = make_float2(s, q);
}
__global__ void ln_finalize(const float2* __restrict__ part, float2* __restrict__ stats) {
    int t = threadIdx.x;
    if (t < BATCH) {
        double s = 0.0, q = 0.0;
        for (int i = 0; i < 128; i++) {
            float2 p = part[t * 128 + i];
            s += (double)p.x; q += (double)p.y;
        }
        double invN = 1.0 / (double)PERB;
        double mu = s * invN;
        double var = q * invN - mu * mu;
        double rstd = 1.0 / sqrt(var + (double)LN_EPS);
        stats[t] = make_float2((float)mu, (float)rstd);
    }
}
__global__ __launch_bounds__(256) void ln_apply(const float* __restrict__ in,
                                                const float* __restrict__ w,
                                                const float* __restrict__ bsh,
                                                const float2* __restrict__ stats,
                                                float* __restrict__ out) {
    size_t i4 = (size_t)blockIdx.x * 256 + threadIdx.x;
    size_t idx = i4 * 4;
    int b = (int)(idx >> 21);
    size_t j = idx & (size_t)(PERB - 1);
    float2 st = stats[b];
    float4 xv = *reinterpret_cast<const float4*>(in + idx);
    float4 wv = *reinterpret_cast<const float4*>(w + j);
    float4 bv = *reinterpret_cast<const float4*>(bsh + j);
    float4 o;
    o.x = (xv.x - st.x) * st.y * wv.x + bv.x;
    o.y = (xv.y - st.x) * st.y * wv.y + bv.y;
    o.z = (xv.z - st.x) * st.y * wv.z + bv.z;
    o.w = (xv.w - st.x) * st.y * wv.w + bv.w;
    *reinterpret_cast<float4*>(out + idx) = o;
}

// ================= weight split fp32 -> bf16 hi/lo =================
__global__ __launch_bounds__(256) void wconv(const float* __restrict__ src,
                                             __nv_bfloat16* __restrict__ h,
                                             __nv_bfloat16* __restrict__ l, int n) {
    int i = blockIdx.x * 256 + threadIdx.x;
    if (i < n) {
        float v = src[i];
        __nv_bfloat16 hi = __float2bfloat16_rn(v);
        h[i] = hi;
        l[i] = __float2bfloat16_rn(v - __bfloat162float(hi));
    }
}

// ============ activation convert+transpose: fp32 (b,C,HW) -> bf16 hi/lo (b,HW,C) ============
__global__ __launch_bounds__(256) void conv_t(const float* __restrict__ in,
                                              __nv_bfloat16* __restrict__ oh,
                                              __nv_bfloat16* __restrict__ ol, int C) {
    __shared__ float T[32][33];
    const int p0 = blockIdx.x * 32, c0 = blockIdx.y * 32, b = blockIdx.z;
    const int t = threadIdx.x;
    {
        int cl = t >> 3, p4 = (t & 7) * 4;
        float4 v = *reinterpret_cast<const float4*>(
            in + ((size_t)b * C + c0 + cl) * HW + p0 + p4);
        T[cl][p4 + 0] = v.x; T[cl][p4 + 1] = v.y; T[cl][p4 + 2] = v.z; T[cl][p4 + 3] = v.w;
    }
    __syncthreads();
    {
        int pl = t >> 3, c4 = (t & 7) * 4;
        unsigned int ph[2], pl2[2];
        #pragma unroll
        for (int k = 0; k < 2; k++) {
            unsigned int hh = 0, ll = 0;
            #pragma unroll
            for (int j = 0; j < 2; j++) {
                float f = T[c4 + k * 2 + j][pl];
                __nv_bfloat16 hi = __float2bfloat16_rn(f);
                __nv_bfloat16 lo = __float2bfloat16_rn(f - __bfloat162float(hi));
                unsigned short hb = *reinterpret_cast<unsigned short*>(&hi);
                unsigned short lb = *reinterpret_cast<unsigned short*>(&lo);
                hh |= (unsigned int)hb << (16 * j);
                ll |= (unsigned int)lb << (16 * j);
            }
            ph[k] = hh; pl2[k] = ll;
        }
        size_t o = ((size_t)b * HW + p0 + pl) * C + c0 + c4;
        *reinterpret_cast<uint2*>(oh + o) = make_uint2(ph[0], ph[1]);
        *reinterpret_cast<uint2*>(ol + o) = make_uint2(pl2[0], pl2[1]);
    }
}

// ================= HMMA bf16x3 GEMM (mma.sync, cp.async 3-stage) =================
// D[m,n] = sum_k W[m,k] * Act[n,k]; W bf16 hi/lo (M,K) row-major; Act bf16 hi/lo (HW,K).
// Both operands fed by NON-trans ldmatrix: A is [m][k] (row), B is [n][k] (= col-major kxn).
// EPI 0: +bias  1: +bias+aux  2: gelu(+bias)  3: +bias, accumulate into Out
#define GSTAGE 40960
template <int EPI>
__global__ __launch_bounds__(256, 1)
void hmma_gemm(const __nv_bfloat16* __restrict__ wh, const __nv_bfloat16* __restrict__ wl,
               const __nv_bfloat16* __restrict__ ah, const __nv_bfloat16* __restrict__ al,
               const float* __restrict__ bias, const float* __restrict__ aux,
               float* __restrict__ Out, int K, int M) {
    extern __shared__ unsigned char smem_raw[];
    const uint32_t sb0 = smem_u32(smem_raw);

    const int tid = threadIdx.x;
    const int lane = tid & 31, wid = tid >> 5;
    const int wm = wid & 3, wn = wid >> 2;           // warp grid 4(m) x 2(n)
    const int n0 = blockIdx.x * 128, m0 = blockIdx.y * 128, b = blockIdx.z;

    const __nv_bfloat16* A0 = wh + (size_t)m0 * K;
    const __nv_bfloat16* A1 = wl + (size_t)m0 * K;
    const __nv_bfloat16* B0 = ah + ((size_t)b * HW + n0) * K;
    const __nv_bfloat16* B1 = al + ((size_t)b * HW + n0) * K;

    // cp.async assignments: 512 16B-chunks per operand region, 2 per thread
    const int id0 = tid, id1 = tid + 256;
    const int r0 = id0 >> 2, c0c = id0 & 3;
    const int r1 = id1 >> 2, c1c = id1 & 3;
    const uint32_t s0 = (uint32_t)(r0 * 80 + c0c * 16);
    const uint32_t s1 = (uint32_t)(r1 * 80 + c1c * 16);
    const size_t g0 = (size_t)r0 * K + c0c * 8;
    const size_t g1 = (size_t)r1 * K + c1c * 8;

    // ldmatrix lane addressing (byte offsets within stage), both NON-trans
    // A: matrices (m0-7,k0-7),(m8-15,k0-7),(m0-7,k8-15),(m8-15,k8-15)
    const uint32_t aoff = (uint32_t)((wm * 32 + (lane & 15)) * 80 + ((lane >> 4) * 8) * 2);
    // B: matrices (n0-7,k0-7),(n0-7,k8-15),(n8-15,k0-7),(n8-15,k8-15)
    const uint32_t boff = (uint32_t)(20480 +
        (wn * 64 + (lane & 7) + ((lane >> 4) << 3)) * 80 + (((lane >> 3) & 1) * 8) * 2);

    float acc[2][8][4];
    #pragma unroll
    for (int i = 0; i < 2; i++)
        #pragma unroll
        for (int j = 0; j < 8; j++)
            #pragma unroll
            for (int q = 0; q < 4; q++) acc[i][j][q] = 0.f;

    const int NIT = K >> 5;

    // prologue: stages 0,1
    #pragma unroll
    for (int s = 0; s < 2; s++) {
        uint32_t sbs = sb0 + s * GSTAGE;
        size_t k0 = (size_t)s * 32;
        cp16(sbs + s0,         A0 + g0 + k0);  cp16(sbs + s1,         A0 + g1 + k0);
        cp16(sbs + 10240 + s0, A1 + g0 + k0);  cp16(sbs + 10240 + s1, A1 + g1 + k0);
        cp16(sbs + 20480 + s0, B0 + g0 + k0);  cp16(sbs + 20480 + s1, B0 + g1 + k0);
        cp16(sbs + 30720 + s0, B1 + g0 + k0);  cp16(sbs + 30720 + s1, B1 + g1 + k0);
        cp_commit();
    }

    int stg = 0;
    for (int it = 0; it < NIT; it++) {
        cp_wait<1>();
        __syncthreads();

        // issue loads for it+2
        if (it + 2 < NIT) {
            int ls = it + 2 - ((it + 2) / 3) * 3;
            uint32_t sbs = sb0 + ls * GSTAGE;
            size_t k0 = (size_t)(it + 2) * 32;
            cp16(sbs + s0,         A0 + g0 + k0);  cp16(sbs + s1,         A0 + g1 + k0);
            cp16(sbs + 10240 + s0, A1 + g0 + k0);  cp16(sbs + 10240 + s1, A1 + g1 + k0);
            cp16(sbs + 20480 + s0, B0 + g0 + k0);  cp16(sbs + 20480 + s1, B0 + g1 + k0);
            cp16(sbs + 30720 + s0, B1 + g0 + k0);  cp16(sbs + 30720 + s1, B1 + g1 + k0);
        }
        cp_commit();

        const uint32_t sbs = sb0 + stg * GSTAGE;
        #pragma unroll
        for (int kk = 0; kk < 2; kk++) {
            const uint32_t kb = kk * 32;   // 16 elems * 2B
            uint32_t ra_h[2][4], ra_l[2][4], rb_h[4][4], rb_l[4][4];
            #pragma unroll
            for (int mi = 0; mi < 2; mi++) {
                ldm_x4(ra_h[mi], sbs + aoff + mi * 1280 + kb);
                ldm_x4(ra_l[mi], sbs + aoff + 10240 + mi * 1280 + kb);
            }
            #pragma unroll
            for (int ni = 0; ni < 4; ni++) {
                ldm_x4(rb_h[ni], sbs + boff + ni * 1280 + kb);
                ldm_x4(rb_l[ni], sbs + boff + 10240 + ni * 1280 + kb);
            }
            #pragma unroll
            for (int mi = 0; mi < 2; mi++)
                #pragma unroll
                for (int ni = 0; ni < 4; ni++)
                    #pragma unroll
                    for (int j = 0; j < 2; j++) {
                        float* c = acc[mi][ni * 2 + j];
                        mma_bf16(c, ra_h[mi], &rb_h[ni][j * 2]);
                        mma_bf16(c, ra_h[mi], &rb_l[ni][j * 2]);
                        mma_bf16(c, ra_l[mi], &rb_h[ni][j * 2]);
                    }
        }
        __syncthreads();
        stg = (stg == 2) ? 0 : stg + 1;
    }

    // ---- epilogue: direct float2 stores (32B sectors) ----
    const int mrow = m0 + wm * 32 + (lane >> 2);
    const int ncol = n0 + wn * 64 + (lane & 3) * 2;
    #pragma unroll
    for (int mi = 0; mi < 2; mi++) {
        const int mA = mrow + mi * 16;
        const float bv0 = __ldg(bias + mA);
        const float bv1 = __ldg(bias + mA + 8);
        #pragma unroll
        for (int nf = 0; nf < 8; nf++) {
            const int n = ncol + nf * 8;
            size_t iA = ((size_t)b * M + mA) * HW + n;
            size_t iB = iA + (size_t)8 * HW;
            float2 v0 = make_float2(acc[mi][nf][0] + bv0, acc[mi][nf][1] + bv0);
            float2 v1 = make_float2(acc[mi][nf][2] + bv1, acc[mi][nf][3] + bv1);
            if (EPI == 2) {
                v0.x = 0.5f * v0.x * (1.0f + erff(v0.x * 0.70710678118654752f));
                v0.y = 0.5f * v0.y * (1.0f + erff(v0.y * 0.70710678118654752f));
                v1.x = 0.5f * v1.x * (1.0f + erff(v1.x * 0.70710678118654752f));
                v1.y = 0.5f * v1.y * (1.0f + erff(v1.y * 0.70710678118654752f));
            } else if (EPI == 1) {
                float2 a0 = *reinterpret_cast<const float2*>(aux + iA);
                float2 a1 = *reinterpret_cast<const float2*>(aux + iB);
                v0.x += a0.x; v0.y += a0.y; v1.x += a1.x; v1.y += a1.y;
            } else if (EPI == 3) {
                float2 a0 = *reinterpret_cast<const float2*>(Out + iA);
                float2 a1 = *reinterpret_cast<const float2*>(Out + iB);
                v0.x += a0.x; v0.y += a0.y; v1.x += a1.x; v1.y += a1.y;
            }
            *reinterpret_cast<float2*>(Out + iA) = v0;
            *reinterpret_cast<float2*>(Out + iB) = v1;
        }
    }
}

// ================= softmaxes =================
__global__ __launch_bounds__(256) void softmax_ch(float* __restrict__ Q) {
    int gid = blockIdx.x * 256 + threadIdx.x;
    int b = gid >> 12, pix = gid & 4095;
    float* base = Q + (size_t)b * PERB + pix;
    float m = -1e30f, s = 0.f;
    for (int c = 0; c < CCH; c++) {
        float v = base[(size_t)c * HW];
        if (v > m) { s = s * expf(m - v) + 1.f; m = v; }
        else       { s += expf(v - m); }
    }
    float inv = 1.f / s;
    for (int c = 0; c < CCH; c++) {
        float v = base[(size_t)c * HW];
        base[(size_t)c * HW] = expf(v - m) * inv;
    }
}
__global__ __launch_bounds__(256) void softmax_sp(float* __restrict__ Kp) {
    float* row = Kp + (size_t)blockIdx.x * HW;
    float4 v[4];
    float m = -1e30f;
    #pragma unroll
    for (int i = 0; i < 4; i++) {
        v[i] = reinterpret_cast<float4*>(row)[threadIdx.x + i * 256];
        m = fmaxf(m, fmaxf(fmaxf(v[i].x, v[i].y), fmaxf(v[i].z, v[i].w)));
    }
    m = bred_max(m);
    float s = 0.f;
    #pragma unroll
    for (int i = 0; i < 4; i++) {
        v[i].x = expf(v[i].x - m); v[i].y = expf(v[i].y - m);
        v[i].z = expf(v[i].z - m); v[i].w = expf(v[i].w - m);
        s += v[i].x + v[i].y + v[i].z + v[i].w;
    }
    s = bred_sum(s);
    float inv = 1.f / s;
    #pragma unroll
    for (int i = 0; i < 4; i++) {
        v[i].x *= inv; v[i].y *= inv; v[i].z *= inv; v[i].w *= inv;
        reinterpret_cast<float4*>(row)[threadIdx.x + i * 256] = v[i];
    }
}

// ================= attention =================
__global__ __launch_bounds__(256) void kv_kernel(const float* __restrict__ Kp,
                                                 const float* __restrict__ Vp,
                                                 float* __restrict__ KV) {
    const int bh = blockIdx.x;
    const float* Kb = Kp + (size_t)bh * HDIM * HW;
    const float* Vb = Vp + (size_t)bh * HDIM * HW;
    __shared__ float Ks[64][65];
    __shared__ float Vs[64][65];
    const int tid = threadIdx.x;
    const int tx = tid & 15, ty = tid >> 4;
    float acc[4][4] = {};
    for (int p0 = 0; p0 < HW; p0 += 64) {
        #pragma unroll
        for (int t = 0; t < 4; t++) {
            int lin = tid + t * 256;
            int r = lin >> 4, c4 = (lin & 15) * 4;
            float4 kv4 = *reinterpret_cast<const float4*>(&Kb[(size_t)r * HW + p0 + c4]);
            float4 vv4 = *reinterpret_cast<const float4*>(&Vb[(size_t)r * HW + p0 + c4]);
            Ks[r][c4 + 0] = kv4.x; Ks[r][c4 + 1] = kv4.y; Ks[r][c4 + 2] = kv4.z; Ks[r][c4 + 3] = kv4.w;
            Vs[r][c4 + 0] = vv4.x; Vs[r][c4 + 1] = vv4.y; Vs[r][c4 + 2] = vv4.z; Vs[r][c4 + 3] = vv4.w;
        }
        __syncthreads();
        #pragma unroll 8
        for (int p = 0; p < 64; p++) {
            float ra[4], rb[4];
            #pragma unroll
            for (int i = 0; i < 4; i++) ra[i] = Ks[ty * 4 + i][p];
            #pragma unroll
            for (int j = 0; j < 4; j++) rb[j] = Vs[tx * 4 + j][p];
            #pragma unroll
            for (int i = 0; i < 4; i++)
                #pragma unroll
                for (int j = 0; j < 4; j++)
                    acc[i][j] = fmaf(ra[i], rb[j], acc[i][j]);
        }
        __syncthreads();
    }
    float* out = KV + (size_t)bh * HDIM * HDIM;
    #pragma unroll
    for (int i = 0; i < 4; i++)
        #pragma unroll
        for (int j = 0; j < 4; j++)
            out[(ty * 4 + i) * HDIM + tx * 4 + j] = acc[i][j];
}
__global__ __launch_bounds__(256) void attn_kernel(const float* __restrict__ KV,
                                                   const float* __restrict__ Qp,
                                                   float* __restrict__ Out) {
    const int bh = blockIdx.y;
    const int p0 = blockIdx.x * 64;
    const float* Qb  = Qp + (size_t)bh * HDIM * HW;
    const float* KVb = KV + (size_t)bh * HDIM * HDIM;
    __shared__ float KVs[64][64];
    __shared__ float Qs[64][68];
    const int tid = threadIdx.x;
    const int tx = tid & 15, ty = tid >> 4;
    #pragma unroll
    for (int t = 0; t < 4; t++) {
        int lin = tid + t * 256;
        int r = lin >> 4, c4 = (lin & 15) * 4;
        *reinterpret_cast<float4*>(&KVs[r][c4]) =
            *reinterpret_cast<const float4*>(&KVb[(size_t)r * HDIM + c4]);
        float4 q4 = *reinterpret_cast<const float4*>(&Qb[(size_t)r * HW + p0 + c4]);
        *reinterpret_cast<float4*>(&Qs[r][c4]) = q4;
    }
    __syncthreads();
    float acc[4][4] = {};
    #pragma unroll 8
    for (int k = 0; k < 64; k++) {
        float4 q4 = *reinterpret_cast<const float4*>(&Qs[k][tx * 4]);
        float4 a4 = *reinterpret_cast<const float4*>(&KVs[k][ty * 4]);
        float ra[4] = {a4.x, a4.y, a4.z, a4.w};
        float rb[4] = {q4.x, q4.y, q4.z, q4.w};
        #pragma unroll
        for (int i = 0; i < 4; i++)
            #pragma unroll
            for (int j = 0; j < 4; j++)
                acc[i][j] = fmaf(ra[i], rb[j], acc[i][j]);
    }
    float* ob = Out + (size_t)bh * HDIM * HW;
    #pragma unroll
    for (int i = 0; i < 4; i++) {
        int v = ty * 4 + i;
        #pragma unroll
        for (int j = 0; j < 4; j++)
            ob[(size_t)v * HW + p0 + tx * 4 + j] = acc[i][j];
    }
}

// ================= launch =================
extern "C" void kernel_launch(void* const* d_in, const int* in_sizes, int n_in,
                              void* d_out, int out_size) {
    const float* x     = (const float*)d_in[0];
    const float* ln1w  = (const float*)d_in[1];
    const float* ln1b  = (const float*)d_in[2];
    const float* qw    = (const float*)d_in[3];
    const float* qb    = (const float*)d_in[4];
    const float* kw    = (const float*)d_in[5];
    const float* kb    = (const float*)d_in[6];
    const float* vw    = (const float*)d_in[7];
    const float* vb    = (const float*)d_in[8];
    const float* huw   = (const float*)d_in[9];
    const float* hub   = (const float*)d_in[10];
    const float* ln2w  = (const float*)d_in[11];
    const float* ln2b  = (const float*)d_in[12];
    const float* ff1w  = (const float*)d_in[13];
    const float* ff1b  = (const float*)d_in[14];
    const float* ff2w  = (const float*)d_in[15];
    const float* ff2b  = (const float*)d_in[16];
    float* out = (float*)d_out;

    float *A, *Q, *K, *V, *F, *KV;
    float2 *part, *stats;
    __nv_bfloat16 *Th, *Tl, *Wh, *Wl;
    cudaGetSymbolAddress((void**)&A, g_A);
    cudaGetSymbolAddress((void**)&Q, g_Q);
    cudaGetSymbolAddress((void**)&K, g_K);
    cudaGetSymbolAddress((void**)&V, g_V);
    cudaGetSymbolAddress((void**)&F, g_F);
    cudaGetSymbolAddress((void**)&KV, g_KV);
    cudaGetSymbolAddress((void**)&part, g_part);
    cudaGetSymbolAddress((void**)&stats, g_stats);
    cudaGetSymbolAddress((void**)&Th, g_Th);
    cudaGetSymbolAddress((void**)&Tl, g_Tl);
    cudaGetSymbolAddress((void**)&Wh, g_Wh);
    cudaGetSymbolAddress((void**)&Wl, g_Wl);

    const int SMEM = 3 * GSTAGE;   // 122880
    cudaFuncSetAttribute(hmma_gemm<0>, cudaFuncAttributeMaxDynamicSharedMemorySize, SMEM);
    cudaFuncSetAttribute(hmma_gemm<1>, cudaFuncAttributeMaxDynamicSharedMemorySize, SMEM);
    cudaFuncSetAttribute(hmma_gemm<2>, cudaFuncAttributeMaxDynamicSharedMemorySize, SMEM);
    cudaFuncSetAttribute(hmma_gemm<3>, cudaFuncAttributeMaxDynamicSharedMemorySize, SMEM);

    // weight splits
    wconv<<<1024, 256>>>(qw,  Wh + WOFF_Q,  Wl + WOFF_Q,  262144);
    wconv<<<1024, 256>>>(kw,  Wh + WOFF_K,  Wl + WOFF_K,  262144);
    wconv<<<1024, 256>>>(vw,  Wh + WOFF_V,  Wl + WOFF_V,  262144);
    wconv<<<1024, 256>>>(huw, Wh + WOFF_HU, Wl + WOFF_HU, 262144);
    wconv<<<4096, 256>>>(ff1w, Wh + WOFF_FF1, Wl + WOFF_FF1, 1048576);
    wconv<<<4096, 256>>>(ff2w, Wh + WOFF_FF2, Wl + WOFF_FF2, 1048576);

    const dim3 gT512(HW / 32, CCH / 32, BATCH);
    const dim3 gT2048(HW / 32, DHID / 32, BATCH);
    const dim3 gG512(HW / 128, CCH / 128, BATCH);   // (32, 4, 16)
    const dim3 gG2048(HW / 128, DHID / 128, BATCH); // (32, 16, 16)

    // a = ln1(x)
    ln_stats<<<dim3(128, BATCH), 256>>>(x, part);
    ln_finalize<<<1, 32>>>(part, stats);
    ln_apply<<<(BATCH * PERB) / 1024, 256>>>(x, ln1w, ln1b, stats, A);

    // Q, K, V via HMMA
    conv_t<<<gT512, 256>>>(A, Th, Tl, CCH);
    hmma_gemm<0><<<gG512, 256, SMEM>>>(Wh + WOFF_Q, Wl + WOFF_Q, Th, Tl, qb, nullptr, Q, CCH, CCH);
    hmma_gemm<0><<<gG512, 256, SMEM>>>(Wh + WOFF_K, Wl + WOFF_K, Th, Tl, kb, nullptr, K, CCH, CCH);
    hmma_gemm<0><<<gG512, 256, SMEM>>>(Wh + WOFF_V, Wl + WOFF_V, Th, Tl, vb, nullptr, V, CCH, CCH);

    softmax_ch<<<(BATCH * HW) / 256, 256>>>(Q);
    softmax_sp<<<BATCH * CCH, 256>>>(K);

    kv_kernel<<<BATCH * NHEAD, 256>>>(K, V, KV);
    attn_kernel<<<dim3(HW / 64, BATCH * NHEAD), 256>>>(KV, Q, A);

    // R = x + hu(attn) -> Q buffer
    conv_t<<<gT512, 256>>>(A, Th, Tl, CCH);
    hmma_gemm<1><<<gG512, 256, SMEM>>>(Wh + WOFF_HU, Wl + WOFF_HU, Th, Tl, hub, x, Q, CCH, CCH);

    // y = ln2(R) -> out
    ln_stats<<<dim3(128, BATCH), 256>>>(Q, part);
    ln_finalize<<<1, 32>>>(part, stats);
    ln_apply<<<(BATCH * PERB) / 1024, 256>>>(Q, ln2w, ln2b, stats, out);

    // F = gelu(ff1(y)); out += ff2(F)
    conv_t<<<gT512, 256>>>(out, Th, Tl, CCH);
    hmma_gemm<2><<<gG2048, 256, SMEM>>>(Wh + WOFF_FF1, Wl + WOFF_FF1, Th, Tl, ff1b, nullptr, F, CCH, DHID);
    conv_t<<<gT2048, 256>>>(F, Th, Tl, DHID);
    hmma_gemm<3><<<gG512, 256, SMEM>>>(Wh + WOFF_FF2, Wl + WOFF_FF2, Th, Tl, ff2b, nullptr, out, DHID, CCH);
}

// round 5
// speedup vs baseline: 2.6764x; 1.3982x over previous
#include <cuda_runtime.h>
#include <cuda_fp16.h>
#include <math.h>
#include <stdint.h>

// ---------------- problem constants ----------------
#define BATCH 16
#define CCH   512
#define HW    4096
#define DHID  2048
#define NHEAD 8
#define HDIM  64
#define PERB  (CCH*HW)
#define LN_EPS 1e-5f

// ---------------- device scratch (allocation-free) ----------------
__device__ float g_A [BATCH*CCH*HW];   // attn output
__device__ float g_Q [BATCH*CCH*HW];   // Q (exp), later R
__device__ float g_K [BATCH*CCH*HW];
__device__ float g_V [BATCH*CCH*HW];
__device__ float g_KV[BATCH*NHEAD*HDIM*HDIM];
__device__ float g_qsum[BATCH*HW];
__device__ float2 g_part[BATCH*128];
__device__ float2 g_stats[BATCH];
// fp16 activations pixel-major (b, p, c)
__device__ __half g_Th[(size_t)BATCH*HW*CCH];
__device__ __half g_Fh[(size_t)BATCH*HW*DHID];
// fp16 hi/lo weights
#define WOFF_Q   0
#define WOFF_K   262144
#define WOFF_V   524288
#define WOFF_HU  786432
#define WOFF_FF1 1048576
#define WOFF_FF2 2097152
#define WTOT     3145728
__device__ __half g_Wh[WTOT];
__device__ __half g_Wl[WTOT];

// ================= PTX helpers =================
__device__ __forceinline__ uint32_t smem_u32(const void* p) {
    uint32_t a;
    asm("{ .reg .u64 t; cvta.to.shared.u64 t, %1; cvt.u32.u64 %0, t; }" : "=r"(a) : "l"(p));
    return a;
}
__device__ __forceinline__ void cp16(uint32_t dst, const void* src) {
    asm volatile("cp.async.cg.shared.global [%0], [%1], 16;" :: "r"(dst), "l"(src));
}
__device__ __forceinline__ void cp_commit() {
    asm volatile("cp.async.commit_group;" ::: "memory");
}
template <int N>
__device__ __forceinline__ void cp_wait() {
    asm volatile("cp.async.wait_group %0;" :: "n"(N) : "memory");
}
__device__ __forceinline__ void ldm_x4(uint32_t* r, uint32_t addr) {
    asm volatile("ldmatrix.sync.aligned.m8n8.x4.shared.b16 {%0,%1,%2,%3}, [%4];"
                 : "=r"(r[0]), "=r"(r[1]), "=r"(r[2]), "=r"(r[3]) : "r"(addr));
}
__device__ __forceinline__ void mma_f16(float* c, const uint32_t* a, const uint32_t* b) {
    asm("mma.sync.aligned.m16n8k16.row.col.f32.f16.f16.f32 "
        "{%0,%1,%2,%3}, {%4,%5,%6,%7}, {%8,%9}, {%0,%1,%2,%3};"
        : "+f"(c[0]), "+f"(c[1]), "+f"(c[2]), "+f"(c[3])
        : "r"(a[0]), "r"(a[1]), "r"(a[2]), "r"(a[3]), "r"(b[0]), "r"(b[1]));
}

// fast exp on FMA pipe: exp(x) = 2^(x*log2e), |rel err| ~1e-7 for |x| < 80
__device__ __forceinline__ float fexp(float x) {
    float t = x * 1.4426950408889634f;
    float n = rintf(t);
    float r = t - n;
    float p = 0.00015403530393381609f;
    p = fmaf(p, r, 0.0013333558146428443f);
    p = fmaf(p, r, 0.009618129107628477f);
    p = fmaf(p, r, 0.05550410866482158f);
    p = fmaf(p, r, 0.2402265069591007f);
    p = fmaf(p, r, 0.6931471805599453f);
    p = fmaf(p, r, 1.0f);
    int e = __float2int_rn(n);
    return p * __int_as_float((e + 127) << 23);
}

// ================= block reductions =================
__device__ __forceinline__ float bred_sum(float v) {
    __shared__ float sb[8];
    int lane = threadIdx.x & 31, w = threadIdx.x >> 5;
    #pragma unroll
    for (int o = 16; o; o >>= 1) v += __shfl_down_sync(0xffffffffu, v, o);
    if (lane == 0) sb[w] = v;
    __syncthreads();
    if (threadIdx.x < 32) {
        float r = (lane < 8) ? sb[lane] : 0.f;
        #pragma unroll
        for (int o = 4; o; o >>= 1) r += __shfl_down_sync(0xffffffffu, r, o);
        if (lane == 0) sb[0] = r;
    }
    __syncthreads();
    float out = sb[0];
    __syncthreads();
    return out;
}

// ================= LayerNorm =================
__global__ __launch_bounds__(256) void ln_stats(const float* __restrict__ in,
                                                float2* __restrict__ part) {
    int b = blockIdx.y, pb = blockIdx.x;
    const float* p = in + (size_t)b * PERB + (size_t)pb * 16384;
    float s = 0.f, q = 0.f;
    #pragma unroll
    for (int i = 0; i < 16; i++) {
        float4 v = *reinterpret_cast<const float4*>(p + (size_t)(threadIdx.x + i * 256) * 4);
        s += v.x + v.y + v.z + v.w;
        q += v.x * v.x + v.y * v.y + v.z * v.z + v.w * v.w;
    }
    s = bred_sum(s);
    q = bred_sum(q);
    if (threadIdx.x == 0) part[b * 128 + pb] = make_float2(s, q);
}
__global__ void ln_finalize(const float2* __restrict__ part, float2* __restrict__ stats) {
    int t = threadIdx.x;
    if (t < BATCH) {
        double s = 0.0, q = 0.0;
        for (int i = 0; i < 128; i++) {
            float2 p = part[t * 128 + i];
            s += (double)p.x; q += (double)p.y;
        }
        double invN = 1.0 / (double)PERB;
        double mu = s * invN;
        double var = q * invN - mu * mu;
        double rstd = 1.0 / sqrt(var + (double)LN_EPS);
        stats[t] = make_float2((float)mu, (float)rstd);
    }
}
__global__ __launch_bounds__(256) void ln_apply(const float* __restrict__ in,
                                                const float* __restrict__ w,
                                                const float* __restrict__ bsh,
                                                const float2* __restrict__ stats,
                                                float* __restrict__ out) {
    size_t i4 = (size_t)blockIdx.x * 256 + threadIdx.x;
    size_t idx = i4 * 4;
    int b = (int)(idx >> 21);
    size_t j = idx & (size_t)(PERB - 1);
    float2 st = stats[b];
    float4 xv = *reinterpret_cast<const float4*>(in + idx);
    float4 wv = *reinterpret_cast<const float4*>(w + j);
    float4 bv = *reinterpret_cast<const float4*>(bsh + j);
    float4 o;
    o.x = (xv.x - st.x) * st.y * wv.x + bv.x;
    o.y = (xv.y - st.x) * st.y * wv.y + bv.y;
    o.z = (xv.z - st.x) * st.y * wv.z + bv.z;
    o.w = (xv.w - st.x) * st.y * wv.w + bv.w;
    *reinterpret_cast<float4*>(out + idx) = o;
}

// ================= weight split fp32 -> fp16 hi/lo =================
__global__ __launch_bounds__(256) void wconv(const float* __restrict__ src,
                                             __half* __restrict__ h,
                                             __half* __restrict__ l, int n) {
    int i = blockIdx.x * 256 + threadIdx.x;
    if (i < n) {
        float v = src[i];
        __half hi = __float2half_rn(v);
        h[i] = hi;
        l[i] = __float2half_rn(v - __half2float(hi));
    }
}

// ===== activation convert+transpose: fp32 (b,C=512,HW) -> fp16 (b,HW,512), optional fused LN =====
template <int DO_LN>
__global__ __launch_bounds__(256) void conv_t(const float* __restrict__ in,
                                              const float* __restrict__ lnw,
                                              const float* __restrict__ lnb,
                                              const float2* __restrict__ stats,
                                              __half* __restrict__ oh) {
    __shared__ float T[32][33];
    const int p0 = blockIdx.x * 32, c0 = blockIdx.y * 32, b = blockIdx.z;
    const int t = threadIdx.x;
    {
        int cl = t >> 3, p4 = (t & 7) * 4;
        size_t gidx = ((size_t)b * CCH + c0 + cl) * HW + p0 + p4;
        float4 v = *reinterpret_cast<const float4*>(in + gidx);
        if (DO_LN) {
            float2 st = stats[b];
            size_t widx = (size_t)(c0 + cl) * HW + p0 + p4;
            float4 wv = *reinterpret_cast<const float4*>(lnw + widx);
            float4 bv = *reinterpret_cast<const float4*>(lnb + widx);
            v.x = (v.x - st.x) * st.y * wv.x + bv.x;
            v.y = (v.y - st.x) * st.y * wv.y + bv.y;
            v.z = (v.z - st.x) * st.y * wv.z + bv.z;
            v.w = (v.w - st.x) * st.y * wv.w + bv.w;
        }
        T[cl][p4 + 0] = v.x; T[cl][p4 + 1] = v.y; T[cl][p4 + 2] = v.z; T[cl][p4 + 3] = v.w;
    }
    __syncthreads();
    {
        int pl = t >> 3, c4 = (t & 7) * 4;
        unsigned short hb[4];
        #pragma unroll
        for (int j = 0; j < 4; j++) {
            __half hv = __float2half_rn(T[c4 + j][pl]);
            hb[j] = *reinterpret_cast<unsigned short*>(&hv);
        }
        uint2 pk;
        pk.x = (unsigned int)hb[0] | ((unsigned int)hb[1] << 16);
        pk.y = (unsigned int)hb[2] | ((unsigned int)hb[3] << 16);
        size_t o = ((size_t)b * HW + p0 + pl) * CCH + c0 + c4;
        *reinterpret_cast<uint2*>(oh + o) = pk;
    }
}

// ================= HMMA fp16x2 GEMM (mma.sync, cp.async 4-stage) =================
// D[m,n] = sum_k W[m,k]*Act[n,k]; W fp16 hi/lo (M,K) row-major; Act fp16 (HW,K) pixel-major.
// EPI 0: +bias -> fp32 (b,M,HW)
// EPI 1: +bias+aux -> fp32
// EPI 2: gelu(+bias) -> fp16 pixel-major OutH (b,HW,M)  [smem transpose]
// EPI 3: +bias, accumulate into fp32 Out
#define GSTAGE 30720
template <int EPI>
__global__ __launch_bounds__(256, 1)
void hmma_gemm(const __half* __restrict__ wh, const __half* __restrict__ wl,
               const __half* __restrict__ ah,
               const float* __restrict__ bias, const float* __restrict__ aux,
               float* __restrict__ Out, __half* __restrict__ OutH, int K, int M) {
    extern __shared__ unsigned char smem_raw[];
    const uint32_t sb0 = smem_u32(smem_raw);

    const int tid = threadIdx.x;
    const int lane = tid & 31, wid = tid >> 5;
    const int wm = wid & 3, wn = wid >> 2;           // warp grid 4(m) x 2(n)
    const int n0 = blockIdx.x * 128, m0 = blockIdx.y * 128, b = blockIdx.z;

    const __half* A0 = wh + (size_t)m0 * K;
    const __half* A1 = wl + (size_t)m0 * K;
    const __half* B0 = ah + ((size_t)b * HW + n0) * K;

    // cp.async: 512 16B-chunks per operand region (128 rows x 4 chunks), 2 per thread
    const int r0 = tid >> 2, c0c = tid & 3;
    const int r1 = (tid + 256) >> 2, c1c = tid & 3;
    const uint32_t s0 = (uint32_t)(r0 * 80 + c0c * 16);
    const uint32_t s1 = (uint32_t)(r1 * 80 + c1c * 16);
    const size_t g0 = (size_t)r0 * K + c0c * 8;
    const size_t g1 = (size_t)r1 * K + c1c * 8;

    // ldmatrix lane addressing (byte offsets within stage), non-trans
    const uint32_t aoff = (uint32_t)((wm * 32 + (lane & 15)) * 80 + (lane >> 4) * 16);
    const uint32_t boff = (uint32_t)(20480 +
        (wn * 64 + (lane & 7) + ((lane >> 4) << 3)) * 80 + ((lane >> 3) & 1) * 16);

    float acc[2][8][4];
    #pragma unroll
    for (int i = 0; i < 2; i++)
        #pragma unroll
        for (int j = 0; j < 8; j++)
            #pragma unroll
            for (int q = 0; q < 4; q++) acc[i][j][q] = 0.f;

    const int NIT = K >> 5;

    // prologue: stages 0..2
    #pragma unroll
    for (int s = 0; s < 3; s++) {
        uint32_t sbs = sb0 + s * GSTAGE;
        size_t k0 = (size_t)s * 32;
        cp16(sbs + s0,         A0 + g0 + k0);  cp16(sbs + s1,         A0 + g1 + k0);
        cp16(sbs + 10240 + s0, A1 + g0 + k0);  cp16(sbs + 10240 + s1, A1 + g1 + k0);
        cp16(sbs + 20480 + s0, B0 + g0 + k0);  cp16(sbs + 20480 + s1, B0 + g1 + k0);
        cp_commit();
    }

    for (int it = 0; it < NIT; it++) {
        cp_wait<2>();
        __syncthreads();

        if (it + 3 < NIT) {
            int ls = (it + 3) & 3;
            uint32_t sbs = sb0 + ls * GSTAGE;
            size_t k0 = (size_t)(it + 3) * 32;
            cp16(sbs + s0,         A0 + g0 + k0);  cp16(sbs + s1,         A0 + g1 + k0);
            cp16(sbs + 10240 + s0, A1 + g0 + k0);  cp16(sbs + 10240 + s1, A1 + g1 + k0);
            cp16(sbs + 20480 + s0, B0 + g0 + k0);  cp16(sbs + 20480 + s1, B0 + g1 + k0);
        }
        cp_commit();

        const uint32_t sbs = sb0 + (it & 3) * GSTAGE;
        #pragma unroll
        for (int kk = 0; kk < 2; kk++) {
            const uint32_t kb = kk * 32;
            uint32_t ra_h[2][4], ra_l[2][4], rb[4][4];
            #pragma unroll
            for (int mi = 0; mi < 2; mi++) {
                ldm_x4(ra_h[mi], sbs + aoff + mi * 1280 + kb);
                ldm_x4(ra_l[mi], sbs + aoff + 10240 + mi * 1280 + kb);
            }
            #pragma unroll
            for (int ni = 0; ni < 4; ni++)
                ldm_x4(rb[ni], sbs + boff + ni * 1280 + kb);
            #pragma unroll
            for (int mi = 0; mi < 2; mi++)
                #pragma unroll
                for (int ni = 0; ni < 4; ni++)
                    #pragma unroll
                    for (int j = 0; j < 2; j++) {
                        float* c = acc[mi][ni * 2 + j];
                        mma_f16(c, ra_h[mi], &rb[ni][j * 2]);
                        mma_f16(c, ra_l[mi], &rb[ni][j * 2]);
                    }
        }
    }

    if (EPI == 2) {
        // gelu(+bias) -> smem transpose -> fp16 pixel-major
        cp_wait<0>();
        __syncthreads();
        unsigned short* T = reinterpret_cast<unsigned short*>(smem_raw);   // [128][144]
        const int lm0 = wm * 32 + (lane >> 2);
        const int ln0 = wn * 64 + (lane & 3) * 2;
        #pragma unroll
        for (int mi = 0; mi < 2; mi++) {
            const int mA = lm0 + mi * 16;
            const float bv0 = __ldg(bias + m0 + mA);
            const float bv1 = __ldg(bias + m0 + mA + 8);
            #pragma unroll
            for (int nf = 0; nf < 8; nf++) {
                const int n = ln0 + nf * 8;
                float v0 = acc[mi][nf][0] + bv0;
                float v1 = acc[mi][nf][1] + bv0;
                float v2 = acc[mi][nf][2] + bv1;
                float v3 = acc[mi][nf][3] + bv1;
                v0 = 0.5f * v0 * (1.0f + erff(v0 * 0.70710678118654752f));
                v1 = 0.5f * v1 * (1.0f + erff(v1 * 0.70710678118654752f));
                v2 = 0.5f * v2 * (1.0f + erff(v2 * 0.70710678118654752f));
                v3 = 0.5f * v3 * (1.0f + erff(v3 * 0.70710678118654752f));
                __half h0 = __float2half_rn(v0), h1 = __float2half_rn(v1);
                __half h2 = __float2half_rn(v2), h3 = __float2half_rn(v3);
                T[n * 144 + mA]           = *reinterpret_cast<unsigned short*>(&h0);
                T[(n + 1) * 144 + mA]     = *reinterpret_cast<unsigned short*>(&h1);
                T[n * 144 + mA + 8]       = *reinterpret_cast<unsigned short*>(&h2);
                T[(n + 1) * 144 + mA + 8] = *reinterpret_cast<unsigned short*>(&h3);
            }
        }
        __syncthreads();
        #pragma unroll
        for (int i = 0; i < 8; i++) {
            int cc = tid + i * 256;           // 2048 chunks: 128 rows x 16 chunks
            int row = cc >> 4, cq = cc & 15;
            uint4 v = *reinterpret_cast<const uint4*>(T + row * 144 + cq * 8);
            size_t o = ((size_t)b * HW + n0 + row) * (size_t)M + m0 + cq * 8;
            *reinterpret_cast<uint4*>(OutH + o) = v;
        }
    } else {
        const int mrow = m0 + wm * 32 + (lane >> 2);
        const int ncol = n0 + wn * 64 + (lane & 3) * 2;
        #pragma unroll
        for (int mi = 0; mi < 2; mi++) {
            const int mA = mrow + mi * 16;
            const float bv0 = __ldg(bias + mA);
            const float bv1 = __ldg(bias + mA + 8);
            #pragma unroll
            for (int nf = 0; nf < 8; nf++) {
                const int n = ncol + nf * 8;
                size_t iA = ((size_t)b * M + mA) * HW + n;
                size_t iB = iA + (size_t)8 * HW;
                float2 v0 = make_float2(acc[mi][nf][0] + bv0, acc[mi][nf][1] + bv0);
                float2 v1 = make_float2(acc[mi][nf][2] + bv1, acc[mi][nf][3] + bv1);
                if (EPI == 1) {
                    float2 a0 = *reinterpret_cast<const float2*>(aux + iA);
                    float2 a1 = *reinterpret_cast<const float2*>(aux + iB);
                    v0.x += a0.x; v0.y += a0.y; v1.x += a1.x; v1.y += a1.y;
                } else if (EPI == 3) {
                    float2 a0 = *reinterpret_cast<const float2*>(Out + iA);
                    float2 a1 = *reinterpret_cast<const float2*>(Out + iB);
                    v0.x += a0.x; v0.y += a0.y; v1.x += a1.x; v1.y += a1.y;
                }
                *reinterpret_cast<float2*>(Out + iA) = v0;
                *reinterpret_cast<float2*>(Out + iB) = v1;
            }
        }
    }
}

// ===== softmax over channels: Q <- exp(Q) in place, per-pixel sum to qsum =====
__global__ __launch_bounds__(256) void softmax_ch(float* __restrict__ Q,
                                                  float* __restrict__ qsum) {
    int gid = blockIdx.x * 256 + threadIdx.x;
    int b = gid >> 12, pix = gid & 4095;
    float* base = Q + (size_t)b * PERB + pix;
    float s = 0.f;
    for (int c = 0; c < CCH; c++) {
        float e = fexp(base[(size_t)c * HW]);
        base[(size_t)c * HW] = e;
        s += e;
    }
    qsum[gid] = s;
}

// ===== softmax over spatial dim, per (b,channel) row, in place (no max; logits ~N(0,1)) =====
__global__ __launch_bounds__(256) void softmax_sp(float* __restrict__ Kp) {
    float* row = Kp + (size_t)blockIdx.x * HW;
    float4 v[4];
    float s = 0.f;
    #pragma unroll
    for (int i = 0; i < 4; i++) {
        v[i] = reinterpret_cast<float4*>(row)[threadIdx.x + i * 256];
        v[i].x = fexp(v[i].x); v[i].y = fexp(v[i].y);
        v[i].z = fexp(v[i].z); v[i].w = fexp(v[i].w);
        s += v[i].x + v[i].y + v[i].z + v[i].w;
    }
    s = bred_sum(s);
    float inv = 1.f / s;
    #pragma unroll
    for (int i = 0; i < 4; i++) {
        v[i].x *= inv; v[i].y *= inv; v[i].z *= inv; v[i].w *= inv;
        reinterpret_cast<float4*>(row)[threadIdx.x + i * 256] = v[i];
    }
}

// ================= attention =================
__global__ __launch_bounds__(256) void kv_kernel(const float* __restrict__ Kp,
                                                 const float* __restrict__ Vp,
                                                 float* __restrict__ KV) {
    const int bh = blockIdx.x;
    const float* Kb = Kp + (size_t)bh * HDIM * HW;
    const float* Vb = Vp + (size_t)bh * HDIM * HW;
    __shared__ float Ks[64][65];
    __shared__ float Vs[64][65];
    const int tid = threadIdx.x;
    const int tx = tid & 15, ty = tid >> 4;
    float acc[4][4] = {};
    for (int p0 = 0; p0 < HW; p0 += 64) {
        #pragma unroll
        for (int t = 0; t < 4; t++) {
            int lin = tid + t * 256;
            int r = lin >> 4, c4 = (lin & 15) * 4;
            float4 kv4 = *reinterpret_cast<const float4*>(&Kb[(size_t)r * HW + p0 + c4]);
            float4 vv4 = *reinterpret_cast<const float4*>(&Vb[(size_t)r * HW + p0 + c4]);
            Ks[r][c4 + 0] = kv4.x; Ks[r][c4 + 1] = kv4.y; Ks[r][c4 + 2] = kv4.z; Ks[r][c4 + 3] = kv4.w;
            Vs[r][c4 + 0] = vv4.x; Vs[r][c4 + 1] = vv4.y; Vs[r][c4 + 2] = vv4.z; Vs[r][c4 + 3] = vv4.w;
        }
        __syncthreads();
        #pragma unroll 8
        for (int p = 0; p < 64; p++) {
            float ra[4], rb[4];
            #pragma unroll
            for (int i = 0; i < 4; i++) ra[i] = Ks[ty * 4 + i][p];
            #pragma unroll
            for (int j = 0; j < 4; j++) rb[j] = Vs[tx * 4 + j][p];
            #pragma unroll
            for (int i = 0; i < 4; i++)
                #pragma unroll
                for (int j = 0; j < 4; j++)
                    acc[i][j] = fmaf(ra[i], rb[j], acc[i][j]);
        }
        __syncthreads();
    }
    float* out = KV + (size_t)bh * HDIM * HDIM;
    #pragma unroll
    for (int i = 0; i < 4; i++)
        #pragma unroll
        for (int j = 0; j < 4; j++)
            out[(ty * 4 + i) * HDIM + tx * 4 + j] = acc[i][j];
}
// attn[v][p] = (sum_k KV[k][v] * expQ[k][p]) / qsum[p]
__global__ __launch_bounds__(256) void attn_kernel(const float* __restrict__ KV,
                                                   const float* __restrict__ Qp,
                                                   const float* __restrict__ qsum,
                                                   float* __restrict__ Out) {
    const int bh = blockIdx.y;
    const int p0 = blockIdx.x * 64;
    const float* Qb  = Qp + (size_t)bh * HDIM * HW;
    const float* KVb = KV + (size_t)bh * HDIM * HDIM;
    __shared__ float KVs[64][64];
    __shared__ float Qs[64][68];
    const int tid = threadIdx.x;
    const int tx = tid & 15, ty = tid >> 4;
    #pragma unroll
    for (int t = 0; t < 4; t++) {
        int lin = tid + t * 256;
        int r = lin >> 4, c4 = (lin & 15) * 4;
        *reinterpret_cast<float4*>(&KVs[r][c4]) =
            *reinterpret_cast<const float4*>(&KVb[(size_t)r * HDIM + c4]);
        float4 q4 = *reinterpret_cast<const float4*>(&Qb[(size_t)r * HW + p0 + c4]);
        *reinterpret_cast<float4*>(&Qs[r][c4]) = q4;
    }
    __syncthreads();
    float acc[4][4] = {};
    #pragma unroll 8
    for (int k = 0; k < 64; k++) {
        float4 q4 = *reinterpret_cast<const float4*>(&Qs[k][tx * 4]);
        float4 a4 = *reinterpret_cast<const float4*>(&KVs[k][ty * 4]);
        float ra[4] = {a4.x, a4.y, a4.z, a4.w};
        float rb[4] = {q4.x, q4.y, q4.z, q4.w};
        #pragma unroll
        for (int i = 0; i < 4; i++)
            #pragma unroll
            for (int j = 0; j < 4; j++)
                acc[i][j] = fmaf(ra[i], rb[j], acc[i][j]);
    }
    const int bq = (bh >> 3) * HW + p0 + tx * 4;
    float inv[4];
    #pragma unroll
    for (int j = 0; j < 4; j++) inv[j] = 1.f / qsum[bq + j];
    float* ob = Out + (size_t)bh * HDIM * HW;
    #pragma unroll
    for (int i = 0; i < 4; i++) {
        int v = ty * 4 + i;
        #pragma unroll
        for (int j = 0; j < 4; j++)
            ob[(size_t)v * HW + p0 + tx * 4 + j] = acc[i][j] * inv[j];
    }
}

// ================= launch =================
extern "C" void kernel_launch(void* const* d_in, const int* in_sizes, int n_in,
                              void* d_out, int out_size) {
    const float* x     = (const float*)d_in[0];
    const float* ln1w  = (const float*)d_in[1];
    const float* ln1b  = (const float*)d_in[2];
    const float* qw    = (const float*)d_in[3];
    const float* qb    = (const float*)d_in[4];
    const float* kw    = (const float*)d_in[5];
    const float* kb    = (const float*)d_in[6];
    const float* vw    = (const float*)d_in[7];
    const float* vb    = (const float*)d_in[8];
    const float* huw   = (const float*)d_in[9];
    const float* hub   = (const float*)d_in[10];
    const float* ln2w  = (const float*)d_in[11];
    const float* ln2b  = (const float*)d_in[12];
    const float* ff1w  = (const float*)d_in[13];
    const float* ff1b  = (const float*)d_in[14];
    const float* ff2w  = (const float*)d_in[15];
    const float* ff2b  = (const float*)d_in[16];
    float* out = (float*)d_out;

    float *A, *Q, *K, *V, *KV, *qsum;
    float2 *part, *stats;
    __half *Th, *Fh, *Wh, *Wl;
    cudaGetSymbolAddress((void**)&A, g_A);
    cudaGetSymbolAddress((void**)&Q, g_Q);
    cudaGetSymbolAddress((void**)&K, g_K);
    cudaGetSymbolAddress((void**)&V, g_V);
    cudaGetSymbolAddress((void**)&KV, g_KV);
    cudaGetSymbolAddress((void**)&qsum, g_qsum);
    cudaGetSymbolAddress((void**)&part, g_part);
    cudaGetSymbolAddress((void**)&stats, g_stats);
    cudaGetSymbolAddress((void**)&Th, g_Th);
    cudaGetSymbolAddress((void**)&Fh, g_Fh);
    cudaGetSymbolAddress((void**)&Wh, g_Wh);
    cudaGetSymbolAddress((void**)&Wl, g_Wl);

    const int SMEM = 4 * GSTAGE;   // 122880
    cudaFuncSetAttribute(hmma_gemm<0>, cudaFuncAttributeMaxDynamicSharedMemorySize, SMEM);
    cudaFuncSetAttribute(hmma_gemm<1>, cudaFuncAttributeMaxDynamicSharedMemorySize, SMEM);
    cudaFuncSetAttribute(hmma_gemm<2>, cudaFuncAttributeMaxDynamicSharedMemorySize, SMEM);
    cudaFuncSetAttribute(hmma_gemm<3>, cudaFuncAttributeMaxDynamicSharedMemorySize, SMEM);

    // weight splits
    wconv<<<1024, 256>>>(qw,  Wh + WOFF_Q,  Wl + WOFF_Q,  262144);
    wconv<<<1024, 256>>>(kw,  Wh + WOFF_K,  Wl + WOFF_K,  262144);
    wconv<<<1024, 256>>>(vw,  Wh + WOFF_V,  Wl + WOFF_V,  262144);
    wconv<<<1024, 256>>>(huw, Wh + WOFF_HU, Wl + WOFF_HU, 262144);
    wconv<<<4096, 256>>>(ff1w, Wh + WOFF_FF1, Wl + WOFF_FF1, 1048576);
    wconv<<<4096, 256>>>(ff2w, Wh + WOFF_FF2, Wl + WOFF_FF2, 1048576);

    const dim3 gT(HW / 32, CCH / 32, BATCH);        // (128, 16, 16)
    const dim3 gG512(HW / 128, CCH / 128, BATCH);   // (32, 4, 16)
    const dim3 gG2048(HW / 128, DHID / 128, BATCH); // (32, 16, 16)

    // ln1 stats; conv_t with fused LN -> Th
    ln_stats<<<dim3(128, BATCH), 256>>>(x, part);
    ln_finalize<<<1, 32>>>(part, stats);
    conv_t<1><<<gT, 256>>>(x, ln1w, ln1b, stats, Th);

    // Q, K, V
    hmma_gemm<0><<<gG512, 256, SMEM>>>(Wh + WOFF_Q, Wl + WOFF_Q, Th, qb, nullptr, Q, nullptr, CCH, CCH);
    hmma_gemm<0><<<gG512, 256, SMEM>>>(Wh + WOFF_K, Wl + WOFF_K, Th, kb, nullptr, K, nullptr, CCH, CCH);
    hmma_gemm<0><<<gG512, 256, SMEM>>>(Wh + WOFF_V, Wl + WOFF_V, Th, vb, nullptr, V, nullptr, CCH, CCH);

    softmax_ch<<<(BATCH * HW) / 256, 256>>>(Q, qsum);
    softmax_sp<<<BATCH * CCH, 256>>>(K);

    kv_kernel<<<BATCH * NHEAD, 256>>>(K, V, KV);
    attn_kernel<<<dim3(HW / 64, BATCH * NHEAD), 256>>>(KV, Q, qsum, A);

    // R = x + hu(attn) -> Q buffer
    conv_t<0><<<gT, 256>>>(A, nullptr, nullptr, nullptr, Th);
    hmma_gemm<1><<<gG512, 256, SMEM>>>(Wh + WOFF_HU, Wl + WOFF_HU, Th, hub, x, Q, nullptr, CCH, CCH);

    // ln2: out = ln2(R); Th = fp16(ln2(R))
    ln_stats<<<dim3(128, BATCH), 256>>>(Q, part);
    ln_finalize<<<1, 32>>>(part, stats);
    ln_apply<<<(BATCH * PERB) / 1024, 256>>>(Q, ln2w, ln2b, stats, out);
    conv_t<1><<<gT, 256>>>(Q, ln2w, ln2b, stats, Th);

    // Fh = fp16(gelu(ff1(y))) pixel-major; out += ff2(Fh)
    hmma_gemm<2><<<gG2048, 256, SMEM>>>(Wh + WOFF_FF1, Wl + WOFF_FF1, Th, ff1b, nullptr, nullptr, Fh, CCH, DHID);
    hmma_gemm<3><<<gG512, 256, SMEM>>>(Wh + WOFF_FF2, Wl + WOFF_FF2, Fh, ff2b, nullptr, out, nullptr, DHID, CCH);
}

// round 6
// speedup vs baseline: 3.9867x; 1.4896x over previous
#include <cuda_runtime.h>
#include <cuda_fp16.h>
#include <math.h>
#include <stdint.h>

// ---------------- problem constants ----------------
#define BATCH 16
#define CCH   512
#define HW    4096
#define DHID  2048
#define NHEAD 8
#define HDIM  64
#define PERB  (CCH*HW)
#define LN_EPS 1e-5f

// ---------------- device scratch (allocation-free) ----------------
__device__ float g_A [BATCH*CCH*HW];   // attn output
__device__ float g_Q [BATCH*CCH*HW];   // Q (exp), later R
__device__ float g_K [BATCH*CCH*HW];
__device__ float g_V [BATCH*CCH*HW];
__device__ float g_KV[BATCH*NHEAD*HDIM*HDIM];
__device__ float g_qsum[BATCH*HW];
__device__ float2 g_part[BATCH*128];
__device__ float2 g_stats[BATCH];
// fp16 activations pixel-major (b, p, c)
__device__ __half g_Th[(size_t)BATCH*HW*CCH];
__device__ __half g_Fh[(size_t)BATCH*HW*DHID];
// fp16 weights (single, rounded)
#define WOFF_Q   0
#define WOFF_K   262144
#define WOFF_V   524288
#define WOFF_HU  786432
#define WOFF_FF1 1048576
#define WOFF_FF2 2097152
#define WTOT     3145728
__device__ __half g_Wh[WTOT];

// ================= PTX helpers =================
__device__ __forceinline__ uint32_t smem_u32(const void* p) {
    uint32_t a;
    asm("{ .reg .u64 t; cvta.to.shared.u64 t, %1; cvt.u32.u64 %0, t; }" : "=r"(a) : "l"(p));
    return a;
}
__device__ __forceinline__ void cp16(uint32_t dst, const void* src) {
    asm volatile("cp.async.cg.shared.global [%0], [%1], 16;" :: "r"(dst), "l"(src));
}
__device__ __forceinline__ void cp_commit() {
    asm volatile("cp.async.commit_group;" ::: "memory");
}
template <int N>
__device__ __forceinline__ void cp_wait() {
    asm volatile("cp.async.wait_group %0;" :: "n"(N) : "memory");
}
__device__ __forceinline__ void ldm_x4(uint32_t* r, uint32_t addr) {
    asm volatile("ldmatrix.sync.aligned.m8n8.x4.shared.b16 {%0,%1,%2,%3}, [%4];"
                 : "=r"(r[0]), "=r"(r[1]), "=r"(r[2]), "=r"(r[3]) : "r"(addr));
}
__device__ __forceinline__ void mma_f16(float* c, const uint32_t* a, const uint32_t* b) {
    asm("mma.sync.aligned.m16n8k16.row.col.f32.f16.f16.f32 "
        "{%0,%1,%2,%3}, {%4,%5,%6,%7}, {%8,%9}, {%0,%1,%2,%3};"
        : "+f"(c[0]), "+f"(c[1]), "+f"(c[2]), "+f"(c[3])
        : "r"(a[0]), "r"(a[1]), "r"(a[2]), "r"(a[3]), "r"(b[0]), "r"(b[1]));
}

// fast exp on FMA pipe
__device__ __forceinline__ float fexp(float x) {
    float t = x * 1.4426950408889634f;
    float n = rintf(t);
    float r = t - n;
    float p = 0.00015403530393381609f;
    p = fmaf(p, r, 0.0013333558146428443f);
    p = fmaf(p, r, 0.009618129107628477f);
    p = fmaf(p, r, 0.05550410866482158f);
    p = fmaf(p, r, 0.2402265069591007f);
    p = fmaf(p, r, 0.6931471805599453f);
    p = fmaf(p, r, 1.0f);
    int e = __float2int_rn(n);
    return p * __int_as_float((e + 127) << 23);
}

// ================= block reductions =================
__device__ __forceinline__ float bred_sum(float v) {
    __shared__ float sb[8];
    int lane = threadIdx.x & 31, w = threadIdx.x >> 5;
    #pragma unroll
    for (int o = 16; o; o >>= 1) v += __shfl_down_sync(0xffffffffu, v, o);
    if (lane == 0) sb[w] = v;
    __syncthreads();
    if (threadIdx.x < 32) {
        float r = (lane < 8) ? sb[lane] : 0.f;
        #pragma unroll
        for (int o = 4; o; o >>= 1) r += __shfl_down_sync(0xffffffffu, r, o);
        if (lane == 0) sb[0] = r;
    }
    __syncthreads();
    float out = sb[0];
    __syncthreads();
    return out;
}

// ================= LayerNorm stats =================
__global__ __launch_bounds__(256) void ln_stats(const float* __restrict__ in,
                                                float2* __restrict__ part) {
    int b = blockIdx.y, pb = blockIdx.x;
    const float* p = in + (size_t)b * PERB + (size_t)pb * 16384;
    float s = 0.f, q = 0.f;
    #pragma unroll
    for (int i = 0; i < 16; i++) {
        float4 v = *reinterpret_cast<const float4*>(p + (size_t)(threadIdx.x + i * 256) * 4);
        s += v.x + v.y + v.z + v.w;
        q += v.x * v.x + v.y * v.y + v.z * v.z + v.w * v.w;
    }
    s = bred_sum(s);
    q = bred_sum(q);
    if (threadIdx.x == 0) part[b * 128 + pb] = make_float2(s, q);
}
__global__ void ln_finalize(const float2* __restrict__ part, float2* __restrict__ stats) {
    int t = threadIdx.x;
    if (t < BATCH) {
        double s = 0.0, q = 0.0;
        for (int i = 0; i < 128; i++) {
            float2 p = part[t * 128 + i];
            s += (double)p.x; q += (double)p.y;
        }
        double invN = 1.0 / (double)PERB;
        double mu = s * invN;
        double var = q * invN - mu * mu;
        double rstd = 1.0 / sqrt(var + (double)LN_EPS);
        stats[t] = make_float2((float)mu, (float)rstd);
    }
}

// ================= weight round fp32 -> fp16 =================
__global__ __launch_bounds__(256) void wconv(const float* __restrict__ src,
                                             __half* __restrict__ h, int n) {
    int i = blockIdx.x * 256 + threadIdx.x;
    if (i < n) h[i] = __float2half_rn(src[i]);
}

// ===== activation convert+transpose: fp32 (b,C=512,HW) -> fp16 (b,HW,512) =====
// DO_LN: apply layernorm using stats; DO_OUT: also write fp32 LN output channel-major
template <int DO_LN, int DO_OUT>
__global__ __launch_bounds__(256) void conv_t(const float* __restrict__ in,
                                              const float* __restrict__ lnw,
                                              const float* __restrict__ lnb,
                                              const float2* __restrict__ stats,
                                              __half* __restrict__ oh,
                                              float* __restrict__ out32) {
    __shared__ float T[32][33];
    const int p0 = blockIdx.x * 32, c0 = blockIdx.y * 32, b = blockIdx.z;
    const int t = threadIdx.x;
    {
        int cl = t >> 3, p4 = (t & 7) * 4;
        size_t gidx = ((size_t)b * CCH + c0 + cl) * HW + p0 + p4;
        float4 v = *reinterpret_cast<const float4*>(in + gidx);
        if (DO_LN) {
            float2 st = stats[b];
            size_t widx = (size_t)(c0 + cl) * HW + p0 + p4;
            float4 wv = *reinterpret_cast<const float4*>(lnw + widx);
            float4 bv = *reinterpret_cast<const float4*>(lnb + widx);
            v.x = (v.x - st.x) * st.y * wv.x + bv.x;
            v.y = (v.y - st.x) * st.y * wv.y + bv.y;
            v.z = (v.z - st.x) * st.y * wv.z + bv.z;
            v.w = (v.w - st.x) * st.y * wv.w + bv.w;
        }
        if (DO_OUT) *reinterpret_cast<float4*>(out32 + gidx) = v;
        T[cl][p4 + 0] = v.x; T[cl][p4 + 1] = v.y; T[cl][p4 + 2] = v.z; T[cl][p4 + 3] = v.w;
    }
    __syncthreads();
    {
        int pl = t >> 3, c4 = (t & 7) * 4;
        unsigned short hb[4];
        #pragma unroll
        for (int j = 0; j < 4; j++) {
            __half hv = __float2half_rn(T[c4 + j][pl]);
            hb[j] = *reinterpret_cast<unsigned short*>(&hv);
        }
        uint2 pk;
        pk.x = (unsigned int)hb[0] | ((unsigned int)hb[1] << 16);
        pk.y = (unsigned int)hb[2] | ((unsigned int)hb[3] << 16);
        size_t o = ((size_t)b * HW + p0 + pl) * CCH + c0 + c4;
        *reinterpret_cast<uint2*>(oh + o) = pk;
    }
}

// ================= HMMA fp16 GEMM (mma.sync, cp.async 4-stage) =================
// D[m,n] = sum_k W[m,k]*Act[n,k]; W fp16 (M,K) row-major; Act fp16 (HW,K) pixel-major.
// EPI 0: +bias -> fp32 (b,M,HW)
// EPI 1: +bias+aux -> fp32
// EPI 2: gelu(+bias) -> fp16 pixel-major OutH (b,HW,M)  [smem transpose]
// EPI 3: +bias, accumulate into fp32 Out
#define GSTAGE 20480
template <int EPI>
__global__ __launch_bounds__(256, 1)
void hmma_gemm(const __half* __restrict__ wh,
               const __half* __restrict__ ah,
               const float* __restrict__ bias, const float* __restrict__ aux,
               float* __restrict__ Out, __half* __restrict__ OutH, int K, int M) {
    extern __shared__ unsigned char smem_raw[];
    const uint32_t sb0 = smem_u32(smem_raw);

    const int tid = threadIdx.x;
    const int lane = tid & 31, wid = tid >> 5;
    const int wm = wid & 3, wn = wid >> 2;           // warp grid 4(m) x 2(n)
    const int n0 = blockIdx.x * 128, m0 = blockIdx.y * 128, b = blockIdx.z;

    const __half* A0 = wh + (size_t)m0 * K;
    const __half* B0 = ah + ((size_t)b * HW + n0) * K;

    // cp.async: 512 16B-chunks per operand region (128 rows x 4 chunks), 2 per thread each
    const int r0 = tid >> 2, c0c = tid & 3;
    const int r1 = (tid + 256) >> 2;
    const uint32_t s0 = (uint32_t)(r0 * 80 + c0c * 16);
    const uint32_t s1 = (uint32_t)(r1 * 80 + c0c * 16);
    const size_t g0 = (size_t)r0 * K + c0c * 8;
    const size_t g1 = (size_t)r1 * K + c0c * 8;

    // ldmatrix lane addressing (byte offsets within stage), non-trans
    const uint32_t aoff = (uint32_t)((wm * 32 + (lane & 15)) * 80 + (lane >> 4) * 16);
    const uint32_t boff = (uint32_t)(10240 +
        (wn * 64 + (lane & 7) + ((lane >> 4) << 3)) * 80 + ((lane >> 3) & 1) * 16);

    float acc[2][8][4];
    #pragma unroll
    for (int i = 0; i < 2; i++)
        #pragma unroll
        for (int j = 0; j < 8; j++)
            #pragma unroll
            for (int q = 0; q < 4; q++) acc[i][j][q] = 0.f;

    const int NIT = K >> 5;

    // prologue: stages 0..2
    #pragma unroll
    for (int s = 0; s < 3; s++) {
        uint32_t sbs = sb0 + s * GSTAGE;
        size_t k0 = (size_t)s * 32;
        cp16(sbs + s0,         A0 + g0 + k0);  cp16(sbs + s1,         A0 + g1 + k0);
        cp16(sbs + 10240 + s0, B0 + g0 + k0);  cp16(sbs + 10240 + s1, B0 + g1 + k0);
        cp_commit();
    }

    for (int it = 0; it < NIT; it++) {
        cp_wait<2>();
        __syncthreads();

        if (it + 3 < NIT) {
            int ls = (it + 3) & 3;
            uint32_t sbs = sb0 + ls * GSTAGE;
            size_t k0 = (size_t)(it + 3) * 32;
            cp16(sbs + s0,         A0 + g0 + k0);  cp16(sbs + s1,         A0 + g1 + k0);
            cp16(sbs + 10240 + s0, B0 + g0 + k0);  cp16(sbs + 10240 + s1, B0 + g1 + k0);
        }
        cp_commit();

        const uint32_t sbs = sb0 + (it & 3) * GSTAGE;
        #pragma unroll
        for (int kk = 0; kk < 2; kk++) {
            const uint32_t kb = kk * 32;
            uint32_t ra[2][4], rb[4][4];
            #pragma unroll
            for (int mi = 0; mi < 2; mi++)
                ldm_x4(ra[mi], sbs + aoff + mi * 1280 + kb);
            #pragma unroll
            for (int ni = 0; ni < 4; ni++)
                ldm_x4(rb[ni], sbs + boff + ni * 1280 + kb);
            #pragma unroll
            for (int mi = 0; mi < 2; mi++)
                #pragma unroll
                for (int ni = 0; ni < 4; ni++)
                    #pragma unroll
                    for (int j = 0; j < 2; j++)
                        mma_f16(acc[mi][ni * 2 + j], ra[mi], &rb[ni][j * 2]);
        }
    }

    if (EPI == 2) {
        // gelu(+bias) -> smem transpose -> fp16 pixel-major
        cp_wait<0>();
        __syncthreads();
        unsigned short* T = reinterpret_cast<unsigned short*>(smem_raw);   // [128][144]
        const int lm0 = wm * 32 + (lane >> 2);
        const int ln0 = wn * 64 + (lane & 3) * 2;
        #pragma unroll
        for (int mi = 0; mi < 2; mi++) {
            const int mA = lm0 + mi * 16;
            const float bv0 = __ldg(bias + m0 + mA);
            const float bv1 = __ldg(bias + m0 + mA + 8);
            #pragma unroll
            for (int nf = 0; nf < 8; nf++) {
                const int n = ln0 + nf * 8;
                float v0 = acc[mi][nf][0] + bv0;
                float v1 = acc[mi][nf][1] + bv0;
                float v2 = acc[mi][nf][2] + bv1;
                float v3 = acc[mi][nf][3] + bv1;
                v0 = 0.5f * v0 * (1.0f + erff(v0 * 0.70710678118654752f));
                v1 = 0.5f * v1 * (1.0f + erff(v1 * 0.70710678118654752f));
                v2 = 0.5f * v2 * (1.0f + erff(v2 * 0.70710678118654752f));
                v3 = 0.5f * v3 * (1.0f + erff(v3 * 0.70710678118654752f));
                __half h0 = __float2half_rn(v0), h1 = __float2half_rn(v1);
                __half h2 = __float2half_rn(v2), h3 = __float2half_rn(v3);
                T[n * 144 + mA]           = *reinterpret_cast<unsigned short*>(&h0);
                T[(n + 1) * 144 + mA]     = *reinterpret_cast<unsigned short*>(&h1);
                T[n * 144 + mA + 8]       = *reinterpret_cast<unsigned short*>(&h2);
                T[(n + 1) * 144 + mA + 8] = *reinterpret_cast<unsigned short*>(&h3);
            }
        }
        __syncthreads();
        #pragma unroll
        for (int i = 0; i < 8; i++) {
            int cc = tid + i * 256;           // 2048 chunks: 128 rows x 16 chunks
            int row = cc >> 4, cq = cc & 15;
            uint4 v = *reinterpret_cast<const uint4*>(T + row * 144 + cq * 8);
            size_t o = ((size_t)b * HW + n0 + row) * (size_t)M + m0 + cq * 8;
            *reinterpret_cast<uint4*>(OutH + o) = v;
        }
    } else {
        const int mrow = m0 + wm * 32 + (lane >> 2);
        const int ncol = n0 + wn * 64 + (lane & 3) * 2;
        #pragma unroll
        for (int mi = 0; mi < 2; mi++) {
            const int mA = mrow + mi * 16;
            const float bv0 = __ldg(bias + mA);
            const float bv1 = __ldg(bias + mA + 8);
            #pragma unroll
            for (int nf = 0; nf < 8; nf++) {
                const int n = ncol + nf * 8;
                size_t iA = ((size_t)b * M + mA) * HW + n;
                size_t iB = iA + (size_t)8 * HW;
                float2 v0 = make_float2(acc[mi][nf][0] + bv0, acc[mi][nf][1] + bv0);
                float2 v1 = make_float2(acc[mi][nf][2] + bv1, acc[mi][nf][3] + bv1);
                if (EPI == 1) {
                    float2 a0 = *reinterpret_cast<const float2*>(aux + iA);
                    float2 a1 = *reinterpret_cast<const float2*>(aux + iB);
                    v0.x += a0.x; v0.y += a0.y; v1.x += a1.x; v1.y += a1.y;
                } else if (EPI == 3) {
                    float2 a0 = *reinterpret_cast<const float2*>(Out + iA);
                    float2 a1 = *reinterpret_cast<const float2*>(Out + iB);
                    v0.x += a0.x; v0.y += a0.y; v1.x += a1.x; v1.y += a1.y;
                }
                *reinterpret_cast<float2*>(Out + iA) = v0;
                *reinterpret_cast<float2*>(Out + iB) = v1;
            }
        }
    }
}

// ===== softmax over channels: Q <- exp(Q) in place, per-pixel sum to qsum =====
__global__ __launch_bounds__(256) void softmax_ch(float* __restrict__ Q,
                                                  float* __restrict__ qsum) {
    int gid = blockIdx.x * 256 + threadIdx.x;
    int b = gid >> 12, pix = gid & 4095;
    float* base = Q + (size_t)b * PERB + pix;
    float s = 0.f;
    for (int c = 0; c < CCH; c++) {
        float e = fexp(base[(size_t)c * HW]);
        base[(size_t)c * HW] = e;
        s += e;
    }
    qsum[gid] = s;
}

// ===== softmax over spatial dim, per (b,channel) row =====
__global__ __launch_bounds__(256) void softmax_sp(float* __restrict__ Kp) {
    float* row = Kp + (size_t)blockIdx.x * HW;
    float4 v[4];
    float s = 0.f;
    #pragma unroll
    for (int i = 0; i < 4; i++) {
        v[i] = reinterpret_cast<float4*>(row)[threadIdx.x + i * 256];
        v[i].x = fexp(v[i].x); v[i].y = fexp(v[i].y);
        v[i].z = fexp(v[i].z); v[i].w = fexp(v[i].w);
        s += v[i].x + v[i].y + v[i].z + v[i].w;
    }
    s = bred_sum(s);
    float inv = 1.f / s;
    #pragma unroll
    for (int i = 0; i < 4; i++) {
        v[i].x *= inv; v[i].y *= inv; v[i].z *= inv; v[i].w *= inv;
        reinterpret_cast<float4*>(row)[threadIdx.x + i * 256] = v[i];
    }
}

// ================= attention =================
__global__ __launch_bounds__(256) void kv_kernel(const float* __restrict__ Kp,
                                                 const float* __restrict__ Vp,
                                                 float* __restrict__ KV) {
    const int bh = blockIdx.x;
    const float* Kb = Kp + (size_t)bh * HDIM * HW;
    const float* Vb = Vp + (size_t)bh * HDIM * HW;
    __shared__ float Ks[64][65];
    __shared__ float Vs[64][65];
    const int tid = threadIdx.x;
    const int tx = tid & 15, ty = tid >> 4;
    float acc[4][4] = {};
    for (int p0 = 0; p0 < HW; p0 += 64) {
        #pragma unroll
        for (int t = 0; t < 4; t++) {
            int lin = tid + t * 256;
            int r = lin >> 4, c4 = (lin & 15) * 4;
            float4 kv4 = *reinterpret_cast<const float4*>(&Kb[(size_t)r * HW + p0 + c4]);
            float4 vv4 = *reinterpret_cast<const float4*>(&Vb[(size_t)r * HW + p0 + c4]);
            Ks[r][c4 + 0] = kv4.x; Ks[r][c4 + 1] = kv4.y; Ks[r][c4 + 2] = kv4.z; Ks[r][c4 + 3] = kv4.w;
            Vs[r][c4 + 0] = vv4.x; Vs[r][c4 + 1] = vv4.y; Vs[r][c4 + 2] = vv4.z; Vs[r][c4 + 3] = vv4.w;
        }
        __syncthreads();
        #pragma unroll 8
        for (int p = 0; p < 64; p++) {
            float ra[4], rb[4];
            #pragma unroll
            for (int i = 0; i < 4; i++) ra[i] = Ks[ty * 4 + i][p];
            #pragma unroll
            for (int j = 0; j < 4; j++) rb[j] = Vs[tx * 4 + j][p];
            #pragma unroll
            for (int i = 0; i < 4; i++)
                #pragma unroll
                for (int j = 0; j < 4; j++)
                    acc[i][j] = fmaf(ra[i], rb[j], acc[i][j]);
        }
        __syncthreads();
    }
    float* out = KV + (size_t)bh * HDIM * HDIM;
    #pragma unroll
    for (int i = 0; i < 4; i++)
        #pragma unroll
        for (int j = 0; j < 4; j++)
            out[(ty * 4 + i) * HDIM + tx * 4 + j] = acc[i][j];
}
__global__ __launch_bounds__(256) void attn_kernel(const float* __restrict__ KV,
                                                   const float* __restrict__ Qp,
                                                   const float* __restrict__ qsum,
                                                   float* __restrict__ Out) {
    const int bh = blockIdx.y;
    const int p0 = blockIdx.x * 64;
    const float* Qb  = Qp + (size_t)bh * HDIM * HW;
    const float* KVb = KV + (size_t)bh * HDIM * HDIM;
    __shared__ float KVs[64][64];
    __shared__ float Qs[64][68];
    const int tid = threadIdx.x;
    const int tx = tid & 15, ty = tid >> 4;
    #pragma unroll
    for (int t = 0; t < 4; t++) {
        int lin = tid + t * 256;
        int r = lin >> 4, c4 = (lin & 15) * 4;
        *reinterpret_cast<float4*>(&KVs[r][c4]) =
            *reinterpret_cast<const float4*>(&KVb[(size_t)r * HDIM + c4]);
        float4 q4 = *reinterpret_cast<const float4*>(&Qb[(size_t)r * HW + p0 + c4]);
        *reinterpret_cast<float4*>(&Qs[r][c4]) = q4;
    }
    __syncthreads();
    float acc[4][4] = {};
    #pragma unroll 8
    for (int k = 0; k < 64; k++) {
        float4 q4 = *reinterpret_cast<const float4*>(&Qs[k][tx * 4]);
        float4 a4 = *reinterpret_cast<const float4*>(&KVs[k][ty * 4]);
        float ra[4] = {a4.x, a4.y, a4.z, a4.w};
        float rb[4] = {q4.x, q4.y, q4.z, q4.w};
        #pragma unroll
        for (int i = 0; i < 4; i++)
            #pragma unroll
            for (int j = 0; j < 4; j++)
                acc[i][j] = fmaf(ra[i], rb[j], acc[i][j]);
    }
    const int bq = (bh >> 3) * HW + p0 + tx * 4;
    float inv[4];
    #pragma unroll
    for (int j = 0; j < 4; j++) inv[j] = 1.f / qsum[bq + j];
    float* ob = Out + (size_t)bh * HDIM * HW;
    #pragma unroll
    for (int i = 0; i < 4; i++) {
        int v = ty * 4 + i;
        #pragma unroll
        for (int j = 0; j < 4; j++)
            ob[(size_t)v * HW + p0 + tx * 4 + j] = acc[i][j] * inv[j];
    }
}

// ================= launch =================
extern "C" void kernel_launch(void* const* d_in, const int* in_sizes, int n_in,
                              void* d_out, int out_size) {
    const float* x     = (const float*)d_in[0];
    const float* ln1w  = (const float*)d_in[1];
    const float* ln1b  = (const float*)d_in[2];
    const float* qw    = (const float*)d_in[3];
    const float* qb    = (const float*)d_in[4];
    const float* kw    = (const float*)d_in[5];
    const float* kb    = (const float*)d_in[6];
    const float* vw    = (const float*)d_in[7];
    const float* vb    = (const float*)d_in[8];
    const float* huw   = (const float*)d_in[9];
    const float* hub   = (const float*)d_in[10];
    const float* ln2w  = (const float*)d_in[11];
    const float* ln2b  = (const float*)d_in[12];
    const float* ff1w  = (const float*)d_in[13];
    const float* ff1b  = (const float*)d_in[14];
    const float* ff2w  = (const float*)d_in[15];
    const float* ff2b  = (const float*)d_in[16];
    float* out = (float*)d_out;

    float *A, *Q, *K, *V, *KV, *qsum;
    float2 *part, *stats;
    __half *Th, *Fh, *Wh;
    cudaGetSymbolAddress((void**)&A, g_A);
    cudaGetSymbolAddress((void**)&Q, g_Q);
    cudaGetSymbolAddress((void**)&K, g_K);
    cudaGetSymbolAddress((void**)&V, g_V);
    cudaGetSymbolAddress((void**)&KV, g_KV);
    cudaGetSymbolAddress((void**)&qsum, g_qsum);
    cudaGetSymbolAddress((void**)&part, g_part);
    cudaGetSymbolAddress((void**)&stats, g_stats);
    cudaGetSymbolAddress((void**)&Th, g_Th);
    cudaGetSymbolAddress((void**)&Fh, g_Fh);
    cudaGetSymbolAddress((void**)&Wh, g_Wh);

    const int SMEM = 4 * GSTAGE;   // 81920
    cudaFuncSetAttribute(hmma_gemm<0>, cudaFuncAttributeMaxDynamicSharedMemorySize, SMEM);
    cudaFuncSetAttribute(hmma_gemm<1>, cudaFuncAttributeMaxDynamicSharedMemorySize, SMEM);
    cudaFuncSetAttribute(hmma_gemm<2>, cudaFuncAttributeMaxDynamicSharedMemorySize, SMEM);
    cudaFuncSetAttribute(hmma_gemm<3>, cudaFuncAttributeMaxDynamicSharedMemorySize, SMEM);

    // weight rounding
    wconv<<<1024, 256>>>(qw,  Wh + WOFF_Q,  262144);
    wconv<<<1024, 256>>>(kw,  Wh + WOFF_K,  262144);
    wconv<<<1024, 256>>>(vw,  Wh + WOFF_V,  262144);
    wconv<<<1024, 256>>>(huw, Wh + WOFF_HU, 262144);
    wconv<<<4096, 256>>>(ff1w, Wh + WOFF_FF1, 1048576);
    wconv<<<4096, 256>>>(ff2w, Wh + WOFF_FF2, 1048576);

    const dim3 gT(HW / 32, CCH / 32, BATCH);        // (128, 16, 16)
    const dim3 gG512(HW / 128, CCH / 128, BATCH);   // (32, 4, 16)
    const dim3 gG2048(HW / 128, DHID / 128, BATCH); // (32, 16, 16)

    // ln1 stats; conv_t with fused LN -> Th
    ln_stats<<<dim3(128, BATCH), 256>>>(x, part);
    ln_finalize<<<1, 32>>>(part, stats);
    conv_t<1, 0><<<gT, 256>>>(x, ln1w, ln1b, stats, Th, nullptr);

    // Q, K, V
    hmma_gemm<0><<<gG512, 256, SMEM>>>(Wh + WOFF_Q, Th, qb, nullptr, Q, nullptr, CCH, CCH);
    hmma_gemm<0><<<gG512, 256, SMEM>>>(Wh + WOFF_K, Th, kb, nullptr, K, nullptr, CCH, CCH);
    hmma_gemm<0><<<gG512, 256, SMEM>>>(Wh + WOFF_V, Th, vb, nullptr, V, nullptr, CCH, CCH);

    softmax_ch<<<(BATCH * HW) / 256, 256>>>(Q, qsum);
    softmax_sp<<<BATCH * CCH, 256>>>(K);

    kv_kernel<<<BATCH * NHEAD, 256>>>(K, V, KV);
    attn_kernel<<<dim3(HW / 64, BATCH * NHEAD), 256>>>(KV, Q, qsum, A);

    // R = x + hu(attn) -> Q buffer
    conv_t<0, 0><<<gT, 256>>>(A, nullptr, nullptr, nullptr, Th, nullptr);
    hmma_gemm<1><<<gG512, 256, SMEM>>>(Wh + WOFF_HU, Th, hub, x, Q, nullptr, CCH, CCH);

    // ln2: fused -> out (fp32) and Th (fp16 pixel-major)
    ln_stats<<<dim3(128, BATCH), 256>>>(Q, part);
    ln_finalize<<<1, 32>>>(part, stats);
    conv_t<1, 1><<<gT, 256>>>(Q, ln2w, ln2b, stats, Th, out);

    // Fh = fp16(gelu(ff1(y))) pixel-major; out += ff2(Fh)
    hmma_gemm<2><<<gG2048, 256, SMEM>>>(Wh + WOFF_FF1, Th, ff1b, nullptr, nullptr, Fh, CCH, DHID);
    hmma_gemm<3><<<gG512, 256, SMEM>>>(Wh + WOFF_FF2, Fh, ff2b, nullptr, out, nullptr, DHID, CCH);
}

// round 7
// speedup vs baseline: 3.9982x; 1.0029x over previous
#include <cuda_runtime.h>
#include <cuda_fp16.h>
#include <math.h>
#include <stdint.h>

// ---------------- problem constants ----------------
#define BATCH 16
#define CCH   512
#define HW    4096
#define DHID  2048
#define NHEAD 8
#define HDIM  64
#define PERB  (CCH*HW)
#define LN_EPS 1e-5f

// ---------------- device scratch (allocation-free) ----------------
__device__ float g_Q [BATCH*CCH*HW];   // expQ, later R
__device__ float g_K [BATCH*CCH*HW];   // expK
__device__ float g_V [BATCH*CCH*HW];
__device__ float g_KV[BATCH*NHEAD*HDIM*HDIM];
__device__ float g_qsum[BATCH*HW];
__device__ float g_kinv[BATCH*CCH];
__device__ float2 g_part[BATCH*128];
__device__ float2 g_stats[BATCH];
// fp16 activations pixel-major (b, p, c)
__device__ __half g_Th[(size_t)BATCH*HW*CCH];
__device__ __half g_Fh[(size_t)BATCH*HW*DHID];
// fp16 weights
#define WOFF_Q   0
#define WOFF_K   262144
#define WOFF_V   524288
#define WOFF_HU  786432
#define WOFF_FF1 1048576
#define WOFF_FF2 2097152
#define WTOT     3145728
__device__ __half g_Wh[WTOT];

// ================= PTX helpers =================
__device__ __forceinline__ uint32_t smem_u32(const void* p) {
    uint32_t a;
    asm("{ .reg .u64 t; cvta.to.shared.u64 t, %1; cvt.u32.u64 %0, t; }" : "=r"(a) : "l"(p));
    return a;
}
__device__ __forceinline__ void cp16(uint32_t dst, const void* src) {
    asm volatile("cp.async.cg.shared.global [%0], [%1], 16;" :: "r"(dst), "l"(src));
}
__device__ __forceinline__ void cp_commit() {
    asm volatile("cp.async.commit_group;" ::: "memory");
}
template <int N>
__device__ __forceinline__ void cp_wait() {
    asm volatile("cp.async.wait_group %0;" :: "n"(N) : "memory");
}
__device__ __forceinline__ void ldm_x4(uint32_t* r, uint32_t addr) {
    asm volatile("ldmatrix.sync.aligned.m8n8.x4.shared.b16 {%0,%1,%2,%3}, [%4];"
                 : "=r"(r[0]), "=r"(r[1]), "=r"(r[2]), "=r"(r[3]) : "r"(addr));
}
__device__ __forceinline__ void mma_f16(float* c, const uint32_t* a, const uint32_t* b) {
    asm("mma.sync.aligned.m16n8k16.row.col.f32.f16.f16.f32 "
        "{%0,%1,%2,%3}, {%4,%5,%6,%7}, {%8,%9}, {%0,%1,%2,%3};"
        : "+f"(c[0]), "+f"(c[1]), "+f"(c[2]), "+f"(c[3])
        : "r"(a[0]), "r"(a[1]), "r"(a[2]), "r"(a[3]), "r"(b[0]), "r"(b[1]));
}

// fast exp on FMA pipe
__device__ __forceinline__ float fexp(float x) {
    float t = x * 1.4426950408889634f;
    float n = rintf(t);
    float r = t - n;
    float p = 0.00015403530393381609f;
    p = fmaf(p, r, 0.0013333558146428443f);
    p = fmaf(p, r, 0.009618129107628477f);
    p = fmaf(p, r, 0.05550410866482158f);
    p = fmaf(p, r, 0.2402265069591007f);
    p = fmaf(p, r, 0.6931471805599453f);
    p = fmaf(p, r, 1.0f);
    int e = __float2int_rn(n);
    return p * __int_as_float((e + 127) << 23);
}

// ================= block reductions =================
__device__ __forceinline__ float bred_sum(float v) {
    __shared__ float sb[8];
    int lane = threadIdx.x & 31, w = threadIdx.x >> 5;
    #pragma unroll
    for (int o = 16; o; o >>= 1) v += __shfl_down_sync(0xffffffffu, v, o);
    if (lane == 0) sb[w] = v;
    __syncthreads();
    if (threadIdx.x < 32) {
        float r = (lane < 8) ? sb[lane] : 0.f;
        #pragma unroll
        for (int o = 4; o; o >>= 1) r += __shfl_down_sync(0xffffffffu, r, o);
        if (lane == 0) sb[0] = r;
    }
    __syncthreads();
    float out = sb[0];
    __syncthreads();
    return out;
}

// ================= LayerNorm stats (for ln1 only) =================
__global__ __launch_bounds__(256) void ln_stats(const float* __restrict__ in,
                                                float2* __restrict__ part) {
    int b = blockIdx.y, pb = blockIdx.x;
    const float* p = in + (size_t)b * PERB + (size_t)pb * 16384;
    float s = 0.f, q = 0.f;
    #pragma unroll
    for (int i = 0; i < 16; i++) {
        float4 v = *reinterpret_cast<const float4*>(p + (size_t)(threadIdx.x + i * 256) * 4);
        s += v.x + v.y + v.z + v.w;
        q += v.x * v.x + v.y * v.y + v.z * v.z + v.w * v.w;
    }
    s = bred_sum(s);
    q = bred_sum(q);
    if (threadIdx.x == 0) part[b * 128 + pb] = make_float2(s, q);
}
__global__ void ln_finalize(const float2* __restrict__ part, float2* __restrict__ stats) {
    int t = threadIdx.x;
    if (t < BATCH) {
        double s = 0.0, q = 0.0;
        for (int i = 0; i < 128; i++) {
            float2 p = part[t * 128 + i];
            s += (double)p.x; q += (double)p.y;
        }
        double invN = 1.0 / (double)PERB;
        double mu = s * invN;
        double var = q * invN - mu * mu;
        double rstd = 1.0 / sqrt(var + (double)LN_EPS);
        stats[t] = make_float2((float)mu, (float)rstd);
    }
}

// ================= weight round fp32 -> fp16 =================
__global__ __launch_bounds__(256) void wconv(const float* __restrict__ src,
                                             __half* __restrict__ h, int n) {
    int i = blockIdx.x * 256 + threadIdx.x;
    if (i < n) h[i] = __float2half_rn(src[i]);
}

// ===== activation convert+transpose: fp32 (b,C=512,HW) -> fp16 (b,HW,512) =====
template <int DO_LN, int DO_OUT>
__global__ __launch_bounds__(256) void conv_t(const float* __restrict__ in,
                                              const float* __restrict__ lnw,
                                              const float* __restrict__ lnb,
                                              const float2* __restrict__ stats,
                                              __half* __restrict__ oh,
                                              float* __restrict__ out32) {
    __shared__ float T[32][33];
    const int p0 = blockIdx.x * 32, c0 = blockIdx.y * 32, b = blockIdx.z;
    const int t = threadIdx.x;
    {
        int cl = t >> 3, p4 = (t & 7) * 4;
        size_t gidx = ((size_t)b * CCH + c0 + cl) * HW + p0 + p4;
        float4 v = *reinterpret_cast<const float4*>(in + gidx);
        if (DO_LN) {
            float2 st = stats[b];
            size_t widx = (size_t)(c0 + cl) * HW + p0 + p4;
            float4 wv = *reinterpret_cast<const float4*>(lnw + widx);
            float4 bv = *reinterpret_cast<const float4*>(lnb + widx);
            v.x = (v.x - st.x) * st.y * wv.x + bv.x;
            v.y = (v.y - st.x) * st.y * wv.y + bv.y;
            v.z = (v.z - st.x) * st.y * wv.z + bv.z;
            v.w = (v.w - st.x) * st.y * wv.w + bv.w;
        }
        if (DO_OUT) *reinterpret_cast<float4*>(out32 + gidx) = v;
        T[cl][p4 + 0] = v.x; T[cl][p4 + 1] = v.y; T[cl][p4 + 2] = v.z; T[cl][p4 + 3] = v.w;
    }
    __syncthreads();
    {
        int pl = t >> 3, c4 = (t & 7) * 4;
        unsigned short hb[4];
        #pragma unroll
        for (int j = 0; j < 4; j++) {
            __half hv = __float2half_rn(T[c4 + j][pl]);
            hb[j] = *reinterpret_cast<unsigned short*>(&hv);
        }
        uint2 pk;
        pk.x = (unsigned int)hb[0] | ((unsigned int)hb[1] << 16);
        pk.y = (unsigned int)hb[2] | ((unsigned int)hb[3] << 16);
        size_t o = ((size_t)b * HW + p0 + pl) * CCH + c0 + c4;
        *reinterpret_cast<uint2*>(oh + o) = pk;
    }
}

// ================= HMMA fp16 GEMM (mma.sync, cp.async 4-stage) =================
// EPI 0: +bias -> fp32          EPI 1: +bias+aux -> fp32, + LN partial sums to part
// EPI 2: gelu(+bias) -> fp16 pixel-major OutH
// EPI 3: +bias, accumulate into fp32 Out
// EPI 4: exp(+bias) -> fp32
#define GSTAGE 20480
template <int EPI>
__global__ __launch_bounds__(256, 1)
void hmma_gemm(const __half* __restrict__ wh,
               const __half* __restrict__ ah,
               const float* __restrict__ bias, const float* __restrict__ aux,
               float* __restrict__ Out, __half* __restrict__ OutH,
               float2* __restrict__ part, int K, int M) {
    extern __shared__ unsigned char smem_raw[];
    const uint32_t sb0 = smem_u32(smem_raw);

    const int tid = threadIdx.x;
    const int lane = tid & 31, wid = tid >> 5;
    const int wm = wid & 3, wn = wid >> 2;
    const int n0 = blockIdx.x * 128, m0 = blockIdx.y * 128, b = blockIdx.z;

    const __half* A0 = wh + (size_t)m0 * K;
    const __half* B0 = ah + ((size_t)b * HW + n0) * K;

    const int r0 = tid >> 2, c0c = tid & 3;
    const int r1 = (tid + 256) >> 2;
    const uint32_t s0 = (uint32_t)(r0 * 80 + c0c * 16);
    const uint32_t s1 = (uint32_t)(r1 * 80 + c0c * 16);
    const size_t g0 = (size_t)r0 * K + c0c * 8;
    const size_t g1 = (size_t)r1 * K + c0c * 8;

    const uint32_t aoff = (uint32_t)((wm * 32 + (lane & 15)) * 80 + (lane >> 4) * 16);
    const uint32_t boff = (uint32_t)(10240 +
        (wn * 64 + (lane & 7) + ((lane >> 4) << 3)) * 80 + ((lane >> 3) & 1) * 16);

    float acc[2][8][4];
    #pragma unroll
    for (int i = 0; i < 2; i++)
        #pragma unroll
        for (int j = 0; j < 8; j++)
            #pragma unroll
            for (int q = 0; q < 4; q++) acc[i][j][q] = 0.f;

    const int NIT = K >> 5;

    #pragma unroll
    for (int s = 0; s < 3; s++) {
        uint32_t sbs = sb0 + s * GSTAGE;
        size_t k0 = (size_t)s * 32;
        cp16(sbs + s0,         A0 + g0 + k0);  cp16(sbs + s1,         A0 + g1 + k0);
        cp16(sbs + 10240 + s0, B0 + g0 + k0);  cp16(sbs + 10240 + s1, B0 + g1 + k0);
        cp_commit();
    }

    for (int it = 0; it < NIT; it++) {
        cp_wait<2>();
        __syncthreads();

        if (it + 3 < NIT) {
            int ls = (it + 3) & 3;
            uint32_t sbs = sb0 + ls * GSTAGE;
            size_t k0 = (size_t)(it + 3) * 32;
            cp16(sbs + s0,         A0 + g0 + k0);  cp16(sbs + s1,         A0 + g1 + k0);
            cp16(sbs + 10240 + s0, B0 + g0 + k0);  cp16(sbs + 10240 + s1, B0 + g1 + k0);
        }
        cp_commit();

        const uint32_t sbs = sb0 + (it & 3) * GSTAGE;
        #pragma unroll
        for (int kk = 0; kk < 2; kk++) {
            const uint32_t kb = kk * 32;
            uint32_t ra[2][4], rb[4][4];
            #pragma unroll
            for (int mi = 0; mi < 2; mi++)
                ldm_x4(ra[mi], sbs + aoff + mi * 1280 + kb);
            #pragma unroll
            for (int ni = 0; ni < 4; ni++)
                ldm_x4(rb[ni], sbs + boff + ni * 1280 + kb);
            #pragma unroll
            for (int mi = 0; mi < 2; mi++)
                #pragma unroll
                for (int ni = 0; ni < 4; ni++)
                    #pragma unroll
                    for (int j = 0; j < 2; j++)
                        mma_f16(acc[mi][ni * 2 + j], ra[mi], &rb[ni][j * 2]);
        }
    }

    if (EPI == 2) {
        cp_wait<0>();
        __syncthreads();
        unsigned short* T = reinterpret_cast<unsigned short*>(smem_raw);   // [128][144]
        const int lm0 = wm * 32 + (lane >> 2);
        const int ln0 = wn * 64 + (lane & 3) * 2;
        #pragma unroll
        for (int mi = 0; mi < 2; mi++) {
            const int mA = lm0 + mi * 16;
            const float bv0 = __ldg(bias + m0 + mA);
            const float bv1 = __ldg(bias + m0 + mA + 8);
            #pragma unroll
            for (int nf = 0; nf < 8; nf++) {
                const int n = ln0 + nf * 8;
                float v0 = acc[mi][nf][0] + bv0;
                float v1 = acc[mi][nf][1] + bv0;
                float v2 = acc[mi][nf][2] + bv1;
                float v3 = acc[mi][nf][3] + bv1;
                v0 = 0.5f * v0 * (1.0f + erff(v0 * 0.70710678118654752f));
                v1 = 0.5f * v1 * (1.0f + erff(v1 * 0.70710678118654752f));
                v2 = 0.5f * v2 * (1.0f + erff(v2 * 0.70710678118654752f));
                v3 = 0.5f * v3 * (1.0f + erff(v3 * 0.70710678118654752f));
                __half h0 = __float2half_rn(v0), h1 = __float2half_rn(v1);
                __half h2 = __float2half_rn(v2), h3 = __float2half_rn(v3);
                T[n * 144 + mA]           = *reinterpret_cast<unsigned short*>(&h0);
                T[(n + 1) * 144 + mA]     = *reinterpret_cast<unsigned short*>(&h1);
                T[n * 144 + mA + 8]       = *reinterpret_cast<unsigned short*>(&h2);
                T[(n + 1) * 144 + mA + 8] = *reinterpret_cast<unsigned short*>(&h3);
            }
        }
        __syncthreads();
        #pragma unroll
        for (int i = 0; i < 8; i++) {
            int cc = tid + i * 256;
            int row = cc >> 4, cq = cc & 15;
            uint4 v = *reinterpret_cast<const uint4*>(T + row * 144 + cq * 8);
            size_t o = ((size_t)b * HW + n0 + row) * (size_t)M + m0 + cq * 8;
            *reinterpret_cast<uint4*>(OutH + o) = v;
        }
    } else {
        const int mrow = m0 + wm * 32 + (lane >> 2);
        const int ncol = n0 + wn * 64 + (lane & 3) * 2;
        float ls = 0.f, lq = 0.f;
        #pragma unroll
        for (int mi = 0; mi < 2; mi++) {
            const int mA = mrow + mi * 16;
            const float bv0 = __ldg(bias + mA);
            const float bv1 = __ldg(bias + mA + 8);
            #pragma unroll
            for (int nf = 0; nf < 8; nf++) {
                const int n = ncol + nf * 8;
                size_t iA = ((size_t)b * M + mA) * HW + n;
                size_t iB = iA + (size_t)8 * HW;
                float2 v0 = make_float2(acc[mi][nf][0] + bv0, acc[mi][nf][1] + bv0);
                float2 v1 = make_float2(acc[mi][nf][2] + bv1, acc[mi][nf][3] + bv1);
                if (EPI == 4) {
                    v0.x = fexp(v0.x); v0.y = fexp(v0.y);
                    v1.x = fexp(v1.x); v1.y = fexp(v1.y);
                } else if (EPI == 1) {
                    float2 a0 = *reinterpret_cast<const float2*>(aux + iA);
                    float2 a1 = *reinterpret_cast<const float2*>(aux + iB);
                    v0.x += a0.x; v0.y += a0.y; v1.x += a1.x; v1.y += a1.y;
                    ls += v0.x + v0.y + v1.x + v1.y;
                    lq += v0.x * v0.x + v0.y * v0.y + v1.x * v1.x + v1.y * v1.y;
                } else if (EPI == 3) {
                    float2 a0 = *reinterpret_cast<const float2*>(Out + iA);
                    float2 a1 = *reinterpret_cast<const float2*>(Out + iB);
                    v0.x += a0.x; v0.y += a0.y; v1.x += a1.x; v1.y += a1.y;
                }
                *reinterpret_cast<float2*>(Out + iA) = v0;
                *reinterpret_cast<float2*>(Out + iB) = v1;
            }
        }
        if (EPI == 1) {
            ls = bred_sum(ls);
            lq = bred_sum(lq);
            if (tid == 0)
                part[b * 128 + blockIdx.y * 32 + blockIdx.x] = make_float2(ls, lq);
        }
    }
}

// ===== qsum: per-pixel sum over channels of expQ (b,512,HW) =====
__global__ __launch_bounds__(256) void colsum(const float* __restrict__ X,
                                              float* __restrict__ qsum) {
    int gid = blockIdx.x * 256 + threadIdx.x;
    int b = gid >> 12, pix = gid & 4095;
    const float* base = X + (size_t)b * PERB + pix;
    float s = 0.f;
    for (int c = 0; c < CCH; c++) s += base[(size_t)c * HW];
    qsum[gid] = s;
}

// ===== kinv: 1/rowsum of expK, one block per (b,channel) row =====
__global__ __launch_bounds__(256) void rowsum_inv(const float* __restrict__ X,
                                                  float* __restrict__ kinv) {
    const float* row = X + (size_t)blockIdx.x * HW;
    float s = 0.f;
    #pragma unroll
    for (int i = 0; i < 4; i++) {
        float4 v = reinterpret_cast<const float4*>(row)[threadIdx.x + i * 256];
        s += v.x + v.y + v.z + v.w;
    }
    s = bred_sum(s);
    if (threadIdx.x == 0) kinv[blockIdx.x] = 1.f / s;
}

// ================= attention =================
// KV[k][v] = kinv[k] * sum_p expK[k,p]*V[v,p]
__global__ __launch_bounds__(256) void kv_kernel(const float* __restrict__ Kp,
                                                 const float* __restrict__ Vp,
                                                 const float* __restrict__ kinv,
                                                 float* __restrict__ KV) {
    const int bh = blockIdx.x;
    const float* Kb = Kp + (size_t)bh * HDIM * HW;
    const float* Vb = Vp + (size_t)bh * HDIM * HW;
    __shared__ float Ks[64][65];
    __shared__ float Vs[64][65];
    const int tid = threadIdx.x;
    const int tx = tid & 15, ty = tid >> 4;
    float acc[4][4] = {};
    for (int p0 = 0; p0 < HW; p0 += 64) {
        #pragma unroll
        for (int t = 0; t < 4; t++) {
            int lin = tid + t * 256;
            int r = lin >> 4, c4 = (lin & 15) * 4;
            float4 kv4 = *reinterpret_cast<const float4*>(&Kb[(size_t)r * HW + p0 + c4]);
            float4 vv4 = *reinterpret_cast<const float4*>(&Vb[(size_t)r * HW + p0 + c4]);
            Ks[r][c4 + 0] = kv4.x; Ks[r][c4 + 1] = kv4.y; Ks[r][c4 + 2] = kv4.z; Ks[r][c4 + 3] = kv4.w;
            Vs[r][c4 + 0] = vv4.x; Vs[r][c4 + 1] = vv4.y; Vs[r][c4 + 2] = vv4.z; Vs[r][c4 + 3] = vv4.w;
        }
        __syncthreads();
        #pragma unroll 8
        for (int p = 0; p < 64; p++) {
            float ra[4], rb[4];
            #pragma unroll
            for (int i = 0; i < 4; i++) ra[i] = Ks[ty * 4 + i][p];
            #pragma unroll
            for (int j = 0; j < 4; j++) rb[j] = Vs[tx * 4 + j][p];
            #pragma unroll
            for (int i = 0; i < 4; i++)
                #pragma unroll
                for (int j = 0; j < 4; j++)
                    acc[i][j] = fmaf(ra[i], rb[j], acc[i][j]);
        }
        __syncthreads();
    }
    float* out = KV + (size_t)bh * HDIM * HDIM;
    #pragma unroll
    for (int i = 0; i < 4; i++) {
        float inv = __ldg(kinv + bh * HDIM + ty * 4 + i);
        #pragma unroll
        for (int j = 0; j < 4; j++)
            out[(ty * 4 + i) * HDIM + tx * 4 + j] = acc[i][j] * inv;
    }
}
// attn -> fp16 pixel-major Th: Th[(b*HW+p)*512 + h*64 + v] = (sum_k KV[k][v]*expQ[k,p]) / qsum[p]
__global__ __launch_bounds__(256) void attn_kernel(const float* __restrict__ KV,
                                                   const float* __restrict__ Qp,
                                                   const float* __restrict__ qsum,
                                                   __half* __restrict__ Th) {
    const int bh = blockIdx.y;
    const int p0 = blockIdx.x * 64;
    const float* Qb  = Qp + (size_t)bh * HDIM * HW;
    const float* KVb = KV + (size_t)bh * HDIM * HDIM;
    __shared__ float KVs[64][64];
    __shared__ float Qs[64][68];
    __shared__ unsigned short TT[64][72];
    const int tid = threadIdx.x;
    const int tx = tid & 15, ty = tid >> 4;
    #pragma unroll
    for (int t = 0; t < 4; t++) {
        int lin = tid + t * 256;
        int r = lin >> 4, c4 = (lin & 15) * 4;
        *reinterpret_cast<float4*>(&KVs[r][c4]) =
            *reinterpret_cast<const float4*>(&KVb[(size_t)r * HDIM + c4]);
        float4 q4 = *reinterpret_cast<const float4*>(&Qb[(size_t)r * HW + p0 + c4]);
        *reinterpret_cast<float4*>(&Qs[r][c4]) = q4;
    }
    __syncthreads();
    float acc[4][4] = {};
    #pragma unroll 8
    for (int k = 0; k < 64; k++) {
        float4 q4 = *reinterpret_cast<const float4*>(&Qs[k][tx * 4]);
        float4 a4 = *reinterpret_cast<const float4*>(&KVs[k][ty * 4]);
        float ra[4] = {a4.x, a4.y, a4.z, a4.w};
        float rb[4] = {q4.x, q4.y, q4.z, q4.w};
        #pragma unroll
        for (int i = 0; i < 4; i++)
            #pragma unroll
            for (int j = 0; j < 4; j++)
                acc[i][j] = fmaf(ra[i], rb[j], acc[i][j]);
    }
    const int b = bh >> 3, h = bh & 7;
    const int bq = b * HW + p0 + tx * 4;
    float inv[4];
    #pragma unroll
    for (int j = 0; j < 4; j++) inv[j] = 1.f / qsum[bq + j];
    #pragma unroll
    for (int i = 0; i < 4; i++)
        #pragma unroll
        for (int j = 0; j < 4; j++) {
            __half hv = __float2half_rn(acc[i][j] * inv[j]);
            TT[tx * 4 + j][ty * 4 + i] = *reinterpret_cast<unsigned short*>(&hv);
        }
    __syncthreads();
    #pragma unroll
    for (int t = 0; t < 2; t++) {
        int cc = tid + t * 256;          // 512 chunks: 64 pixels x 8 (8-half chunks)
        int p = cc >> 3, co = (cc & 7) * 8;
        uint4 v = *reinterpret_cast<const uint4*>(&TT[p][co]);
        size_t o = ((size_t)b * HW + p0 + p) * CCH + h * 64 + co;
        *reinterpret_cast<uint4*>(Th + o) = v;
    }
}

// ================= launch =================
extern "C" void kernel_launch(void* const* d_in, const int* in_sizes, int n_in,
                              void* d_out, int out_size) {
    const float* x     = (const float*)d_in[0];
    const float* ln1w  = (const float*)d_in[1];
    const float* ln1b  = (const float*)d_in[2];
    const float* qw    = (const float*)d_in[3];
    const float* qb    = (const float*)d_in[4];
    const float* kw    = (const float*)d_in[5];
    const float* kb    = (const float*)d_in[6];
    const float* vw    = (const float*)d_in[7];
    const float* vb    = (const float*)d_in[8];
    const float* huw   = (const float*)d_in[9];
    const float* hub   = (const float*)d_in[10];
    const float* ln2w  = (const float*)d_in[11];
    const float* ln2b  = (const float*)d_in[12];
    const float* ff1w  = (const float*)d_in[13];
    const float* ff1b  = (const float*)d_in[14];
    const float* ff2w  = (const float*)d_in[15];
    const float* ff2b  = (const float*)d_in[16];
    float* out = (float*)d_out;

    float *Q, *K, *V, *KV, *qsum, *kinv;
    float2 *part, *stats;
    __half *Th, *Fh, *Wh;
    cudaGetSymbolAddress((void**)&Q, g_Q);
    cudaGetSymbolAddress((void**)&K, g_K);
    cudaGetSymbolAddress((void**)&V, g_V);
    cudaGetSymbolAddress((void**)&KV, g_KV);
    cudaGetSymbolAddress((void**)&qsum, g_qsum);
    cudaGetSymbolAddress((void**)&kinv, g_kinv);
    cudaGetSymbolAddress((void**)&part, g_part);
    cudaGetSymbolAddress((void**)&stats, g_stats);
    cudaGetSymbolAddress((void**)&Th, g_Th);
    cudaGetSymbolAddress((void**)&Fh, g_Fh);
    cudaGetSymbolAddress((void**)&Wh, g_Wh);

    const int SMEM = 4 * GSTAGE;   // 81920
    cudaFuncSetAttribute(hmma_gemm<0>, cudaFuncAttributeMaxDynamicSharedMemorySize, SMEM);
    cudaFuncSetAttribute(hmma_gemm<1>, cudaFuncAttributeMaxDynamicSharedMemorySize, SMEM);
    cudaFuncSetAttribute(hmma_gemm<2>, cudaFuncAttributeMaxDynamicSharedMemorySize, SMEM);
    cudaFuncSetAttribute(hmma_gemm<3>, cudaFuncAttributeMaxDynamicSharedMemorySize, SMEM);
    cudaFuncSetAttribute(hmma_gemm<4>, cudaFuncAttributeMaxDynamicSharedMemorySize, SMEM);

    // weight rounding
    wconv<<<1024, 256>>>(qw,  Wh + WOFF_Q,  262144);
    wconv<<<1024, 256>>>(kw,  Wh + WOFF_K,  262144);
    wconv<<<1024, 256>>>(vw,  Wh + WOFF_V,  262144);
    wconv<<<1024, 256>>>(huw, Wh + WOFF_HU, 262144);
    wconv<<<4096, 256>>>(ff1w, Wh + WOFF_FF1, 1048576);
    wconv<<<4096, 256>>>(ff2w, Wh + WOFF_FF2, 1048576);

    const dim3 gT(HW / 32, CCH / 32, BATCH);        // (128, 16, 16)
    const dim3 gG512(HW / 128, CCH / 128, BATCH);   // (32, 4, 16)
    const dim3 gG2048(HW / 128, DHID / 128, BATCH); // (32, 16, 16)

    // ln1 -> Th
    ln_stats<<<dim3(128, BATCH), 256>>>(x, part);
    ln_finalize<<<1, 32>>>(part, stats);
    conv_t<1, 0><<<gT, 256>>>(x, ln1w, ln1b, stats, Th, nullptr);

    // expQ, expK, V
    hmma_gemm<4><<<gG512, 256, SMEM>>>(Wh + WOFF_Q, Th, qb, nullptr, Q, nullptr, nullptr, CCH, CCH);
    hmma_gemm<4><<<gG512, 256, SMEM>>>(Wh + WOFF_K, Th, kb, nullptr, K, nullptr, nullptr, CCH, CCH);
    hmma_gemm<0><<<gG512, 256, SMEM>>>(Wh + WOFF_V, Th, vb, nullptr, V, nullptr, nullptr, CCH, CCH);

    colsum<<<(BATCH * HW) / 256, 256>>>(Q, qsum);
    rowsum_inv<<<BATCH * CCH, 256>>>(K, kinv);

    kv_kernel<<<BATCH * NHEAD, 256>>>(K, V, kinv, KV);
    attn_kernel<<<dim3(HW / 64, BATCH * NHEAD), 256>>>(KV, Q, qsum, Th);  // -> Th fp16

    // R = x + hu(attn) -> Q; LN2 partials fused
    hmma_gemm<1><<<gG512, 256, SMEM>>>(Wh + WOFF_HU, Th, hub, x, Q, nullptr, part, CCH, CCH);
    ln_finalize<<<1, 32>>>(part, stats);

    // ln2 fused: out (fp32) + Th (fp16 pixel-major)
    conv_t<1, 1><<<gT, 256>>>(Q, ln2w, ln2b, stats, Th, out);

    // Fh = fp16(gelu(ff1)); out += ff2(Fh)
    hmma_gemm<2><<<gG2048, 256, SMEM>>>(Wh + WOFF_FF1, Th, ff1b, nullptr, nullptr, Fh, nullptr, CCH, DHID);
    hmma_gemm<3><<<gG512, 256, SMEM>>>(Wh + WOFF_FF2, Fh, ff2b, nullptr, out, nullptr, nullptr, DHID, CCH);
}

// round 8
// speedup vs baseline: 4.3305x; 1.0831x over previous
#include <cuda_runtime.h>
#include <cuda_fp16.h>
#include <math.h>
#include <stdint.h>

// ---------------- problem constants ----------------
#define BATCH 16
#define CCH   512
#define HW    4096
#define DHID  2048
#define NHEAD 8
#define HDIM  64
#define PERB  (CCH*HW)
#define LN_EPS 1e-5f

// ---------------- device scratch (allocation-free) ----------------
__device__ float g_QKV[(size_t)BATCH*3*PERB];   // expQ/expK/V per batch: (b, 1536, HW)
__device__ float g_R  [BATCH*PERB];             // residual R = x + hu(attn)
__device__ float g_KVp[8*128*HDIM*HDIM];        // split-K partials
__device__ float g_KV [BATCH*NHEAD*HDIM*HDIM];
__device__ float g_qsum[BATCH*HW];
__device__ float g_kinv[BATCH*CCH];
__device__ float g_bqkv[3*CCH];
__device__ float2 g_part[BATCH*128];
__device__ float2 g_stats[BATCH];
// fp16 activations pixel-major (b, p, c)
__device__ __half g_Th[(size_t)BATCH*HW*CCH];
__device__ __half g_Fh[(size_t)BATCH*HW*DHID];
// fp16 weights (stacked: q,k,v,hu,ff1,ff2)
#define WOFF_HU  786432
#define WOFF_FF1 1048576
#define WOFF_FF2 2097152
#define WTOT     3145728
__device__ __half g_Wh[WTOT];

// ================= PTX helpers =================
__device__ __forceinline__ uint32_t smem_u32(const void* p) {
    uint32_t a;
    asm("{ .reg .u64 t; cvta.to.shared.u64 t, %1; cvt.u32.u64 %0, t; }" : "=r"(a) : "l"(p));
    return a;
}
__device__ __forceinline__ void cp16(uint32_t dst, const void* src) {
    asm volatile("cp.async.cg.shared.global [%0], [%1], 16;" :: "r"(dst), "l"(src));
}
__device__ __forceinline__ void cp_commit() {
    asm volatile("cp.async.commit_group;" ::: "memory");
}
template <int N>
__device__ __forceinline__ void cp_wait() {
    asm volatile("cp.async.wait_group %0;" :: "n"(N) : "memory");
}
__device__ __forceinline__ void ldm_x4(uint32_t* r, uint32_t addr) {
    asm volatile("ldmatrix.sync.aligned.m8n8.x4.shared.b16 {%0,%1,%2,%3}, [%4];"
                 : "=r"(r[0]), "=r"(r[1]), "=r"(r[2]), "=r"(r[3]) : "r"(addr));
}
__device__ __forceinline__ void mma_f16(float* c, const uint32_t* a, const uint32_t* b) {
    asm("mma.sync.aligned.m16n8k16.row.col.f32.f16.f16.f32 "
        "{%0,%1,%2,%3}, {%4,%5,%6,%7}, {%8,%9}, {%0,%1,%2,%3};"
        : "+f"(c[0]), "+f"(c[1]), "+f"(c[2]), "+f"(c[3])
        : "r"(a[0]), "r"(a[1]), "r"(a[2]), "r"(a[3]), "r"(b[0]), "r"(b[1]));
}

// fast exp on FMA pipe
__device__ __forceinline__ float fexp(float x) {
    float t = x * 1.4426950408889634f;
    float n = rintf(t);
    float r = t - n;
    float p = 0.00015403530393381609f;
    p = fmaf(p, r, 0.0013333558146428443f);
    p = fmaf(p, r, 0.009618129107628477f);
    p = fmaf(p, r, 0.05550410866482158f);
    p = fmaf(p, r, 0.2402265069591007f);
    p = fmaf(p, r, 0.6931471805599453f);
    p = fmaf(p, r, 1.0f);
    int e = __float2int_rn(n);
    return p * __int_as_float((e + 127) << 23);
}

// ================= block reductions =================
__device__ __forceinline__ float bred_sum(float v) {
    __shared__ float sb[8];
    int lane = threadIdx.x & 31, w = threadIdx.x >> 5;
    #pragma unroll
    for (int o = 16; o; o >>= 1) v += __shfl_down_sync(0xffffffffu, v, o);
    if (lane == 0) sb[w] = v;
    __syncthreads();
    if (threadIdx.x < 32) {
        float r = (lane < 8) ? sb[lane] : 0.f;
        #pragma unroll
        for (int o = 4; o; o >>= 1) r += __shfl_down_sync(0xffffffffu, r, o);
        if (lane == 0) sb[0] = r;
    }
    __syncthreads();
    float out = sb[0];
    __syncthreads();
    return out;
}

// ================= weight conversion (single launch) =================
__global__ __launch_bounds__(256) void wconv_all(const float* __restrict__ qw,
                                                 const float* __restrict__ kw,
                                                 const float* __restrict__ vw,
                                                 const float* __restrict__ huw,
                                                 const float* __restrict__ ff1w,
                                                 const float* __restrict__ ff2w,
                                                 __half* __restrict__ h) {
    int i = blockIdx.x * 256 + threadIdx.x;
    float v;
    if (i < 786432) {
        int seg = i >> 18, off = i & 262143;
        v = (seg == 0) ? qw[off] : (seg == 1) ? kw[off] : vw[off];
    } else if (i < 1048576) {
        v = huw[i - 786432];
    } else if (i < 2097152) {
        v = ff1w[i - 1048576];
    } else {
        v = ff2w[i - 2097152];
    }
    h[i] = __float2half_rn(v);
}
__global__ void pack_bias(const float* __restrict__ qb, const float* __restrict__ kb,
                          const float* __restrict__ vb, float* __restrict__ bq) {
    int i = blockIdx.x * 768 + threadIdx.x;
    if (i < 512) bq[i] = qb[i];
    else if (i < 1024) bq[i] = kb[i - 512];
    else if (i < 1536) bq[i] = vb[i - 1024];
}

// ================= LayerNorm stats (ln1) =================
__global__ __launch_bounds__(256) void ln_stats(const float* __restrict__ in,
                                                float2* __restrict__ part) {
    int b = blockIdx.y, pb = blockIdx.x;
    const float* p = in + (size_t)b * PERB + (size_t)pb * 16384;
    float s = 0.f, q = 0.f;
    #pragma unroll
    for (int i = 0; i < 16; i++) {
        float4 v = *reinterpret_cast<const float4*>(p + (size_t)(threadIdx.x + i * 256) * 4);
        s += v.x + v.y + v.z + v.w;
        q += v.x * v.x + v.y * v.y + v.z * v.z + v.w * v.w;
    }
    s = bred_sum(s);
    q = bred_sum(q);
    if (threadIdx.x == 0) part[b * 128 + pb] = make_float2(s, q);
}
__global__ void ln_finalize(const float2* __restrict__ part, float2* __restrict__ stats) {
    int t = threadIdx.x;
    if (t < BATCH) {
        double s = 0.0, q = 0.0;
        for (int i = 0; i < 128; i++) {
            float2 p = part[t * 128 + i];
            s += (double)p.x; q += (double)p.y;
        }
        double invN = 1.0 / (double)PERB;
        double mu = s * invN;
        double var = q * invN - mu * mu;
        double rstd = 1.0 / sqrt(var + (double)LN_EPS);
        stats[t] = make_float2((float)mu, (float)rstd);
    }
}

// ===== activation convert+transpose: fp32 (b,512,HW) -> fp16 (b,HW,512) =====
template <int DO_LN, int DO_OUT>
__global__ __launch_bounds__(256) void conv_t(const float* __restrict__ in,
                                              const float* __restrict__ lnw,
                                              const float* __restrict__ lnb,
                                              const float2* __restrict__ stats,
                                              __half* __restrict__ oh,
                                              float* __restrict__ out32) {
    __shared__ float T[32][33];
    const int p0 = blockIdx.x * 32, c0 = blockIdx.y * 32, b = blockIdx.z;
    const int t = threadIdx.x;
    {
        int cl = t >> 3, p4 = (t & 7) * 4;
        size_t gidx = ((size_t)b * CCH + c0 + cl) * HW + p0 + p4;
        float4 v = *reinterpret_cast<const float4*>(in + gidx);
        if (DO_LN) {
            float2 st = stats[b];
            size_t widx = (size_t)(c0 + cl) * HW + p0 + p4;
            float4 wv = *reinterpret_cast<const float4*>(lnw + widx);
            float4 bv = *reinterpret_cast<const float4*>(lnb + widx);
            v.x = (v.x - st.x) * st.y * wv.x + bv.x;
            v.y = (v.y - st.x) * st.y * wv.y + bv.y;
            v.z = (v.z - st.x) * st.y * wv.z + bv.z;
            v.w = (v.w - st.x) * st.y * wv.w + bv.w;
        }
        if (DO_OUT) *reinterpret_cast<float4*>(out32 + gidx) = v;
        T[cl][p4 + 0] = v.x; T[cl][p4 + 1] = v.y; T[cl][p4 + 2] = v.z; T[cl][p4 + 3] = v.w;
    }
    __syncthreads();
    {
        int pl = t >> 3, c4 = (t & 7) * 4;
        unsigned short hb[4];
        #pragma unroll
        for (int j = 0; j < 4; j++) {
            __half hv = __float2half_rn(T[c4 + j][pl]);
            hb[j] = *reinterpret_cast<unsigned short*>(&hv);
        }
        uint2 pk;
        pk.x = (unsigned int)hb[0] | ((unsigned int)hb[1] << 16);
        pk.y = (unsigned int)hb[2] | ((unsigned int)hb[3] << 16);
        size_t o = ((size_t)b * HW + p0 + pl) * CCH + c0 + c4;
        *reinterpret_cast<uint2*>(oh + o) = pk;
    }
}

// ================= HMMA fp16 GEMM (mma.sync, cp.async 4-stage) =================
// EPI 1: +bias+aux -> fp32, + LN partial sums    EPI 2: gelu(+bias) -> fp16 pixel-major
// EPI 3: +bias accumulate into Out               EPI 5: exp(+bias) if m0<1024 else +bias (QKV)
#define GSTAGE 20480
template <int EPI>
__global__ __launch_bounds__(256, 1)
void hmma_gemm(const __half* __restrict__ wh,
               const __half* __restrict__ ah,
               const float* __restrict__ bias, const float* __restrict__ aux,
               float* __restrict__ Out, __half* __restrict__ OutH,
               float2* __restrict__ part, int K, int M) {
    extern __shared__ unsigned char smem_raw[];
    const uint32_t sb0 = smem_u32(smem_raw);

    const int tid = threadIdx.x;
    const int lane = tid & 31, wid = tid >> 5;
    const int wm = wid & 3, wn = wid >> 2;
    const int n0 = blockIdx.x * 128, m0 = blockIdx.y * 128, b = blockIdx.z;

    const __half* A0 = wh + (size_t)m0 * K;
    const __half* B0 = ah + ((size_t)b * HW + n0) * K;

    const int r0 = tid >> 2, c0c = tid & 3;
    const int r1 = (tid + 256) >> 2;
    const uint32_t s0 = (uint32_t)(r0 * 80 + c0c * 16);
    const uint32_t s1 = (uint32_t)(r1 * 80 + c0c * 16);
    const size_t g0 = (size_t)r0 * K + c0c * 8;
    const size_t g1 = (size_t)r1 * K + c0c * 8;

    const uint32_t aoff = (uint32_t)((wm * 32 + (lane & 15)) * 80 + (lane >> 4) * 16);
    const uint32_t boff = (uint32_t)(10240 +
        (wn * 64 + (lane & 7) + ((lane >> 4) << 3)) * 80 + ((lane >> 3) & 1) * 16);

    float acc[2][8][4];
    #pragma unroll
    for (int i = 0; i < 2; i++)
        #pragma unroll
        for (int j = 0; j < 8; j++)
            #pragma unroll
            for (int q = 0; q < 4; q++) acc[i][j][q] = 0.f;

    const int NIT = K >> 5;

    #pragma unroll
    for (int s = 0; s < 3; s++) {
        uint32_t sbs = sb0 + s * GSTAGE;
        size_t k0 = (size_t)s * 32;
        cp16(sbs + s0,         A0 + g0 + k0);  cp16(sbs + s1,         A0 + g1 + k0);
        cp16(sbs + 10240 + s0, B0 + g0 + k0);  cp16(sbs + 10240 + s1, B0 + g1 + k0);
        cp_commit();
    }

    for (int it = 0; it < NIT; it++) {
        cp_wait<2>();
        __syncthreads();

        if (it + 3 < NIT) {
            int ls = (it + 3) & 3;
            uint32_t sbs = sb0 + ls * GSTAGE;
            size_t k0 = (size_t)(it + 3) * 32;
            cp16(sbs + s0,         A0 + g0 + k0);  cp16(sbs + s1,         A0 + g1 + k0);
            cp16(sbs + 10240 + s0, B0 + g0 + k0);  cp16(sbs + 10240 + s1, B0 + g1 + k0);
        }
        cp_commit();

        const uint32_t sbs = sb0 + (it & 3) * GSTAGE;
        #pragma unroll
        for (int kk = 0; kk < 2; kk++) {
            const uint32_t kb = kk * 32;
            uint32_t ra[2][4], rb[4][4];
            #pragma unroll
            for (int mi = 0; mi < 2; mi++)
                ldm_x4(ra[mi], sbs + aoff + mi * 1280 + kb);
            #pragma unroll
            for (int ni = 0; ni < 4; ni++)
                ldm_x4(rb[ni], sbs + boff + ni * 1280 + kb);
            #pragma unroll
            for (int mi = 0; mi < 2; mi++)
                #pragma unroll
                for (int ni = 0; ni < 4; ni++)
                    #pragma unroll
                    for (int j = 0; j < 2; j++)
                        mma_f16(acc[mi][ni * 2 + j], ra[mi], &rb[ni][j * 2]);
        }
    }

    if (EPI == 2) {
        cp_wait<0>();
        __syncthreads();
        unsigned short* T = reinterpret_cast<unsigned short*>(smem_raw);   // [128][144]
        const int lm0 = wm * 32 + (lane >> 2);
        const int ln0 = wn * 64 + (lane & 3) * 2;
        #pragma unroll
        for (int mi = 0; mi < 2; mi++) {
            const int mA = lm0 + mi * 16;
            const float bv0 = __ldg(bias + m0 + mA);
            const float bv1 = __ldg(bias + m0 + mA + 8);
            #pragma unroll
            for (int nf = 0; nf < 8; nf++) {
                const int n = ln0 + nf * 8;
                float v0 = acc[mi][nf][0] + bv0;
                float v1 = acc[mi][nf][1] + bv0;
                float v2 = acc[mi][nf][2] + bv1;
                float v3 = acc[mi][nf][3] + bv1;
                v0 = 0.5f * v0 * (1.0f + erff(v0 * 0.70710678118654752f));
                v1 = 0.5f * v1 * (1.0f + erff(v1 * 0.70710678118654752f));
                v2 = 0.5f * v2 * (1.0f + erff(v2 * 0.70710678118654752f));
                v3 = 0.5f * v3 * (1.0f + erff(v3 * 0.70710678118654752f));
                __half h0 = __float2half_rn(v0), h1 = __float2half_rn(v1);
                __half h2 = __float2half_rn(v2), h3 = __float2half_rn(v3);
                T[n * 144 + mA]           = *reinterpret_cast<unsigned short*>(&h0);
                T[(n + 1) * 144 + mA]     = *reinterpret_cast<unsigned short*>(&h1);
                T[n * 144 + mA + 8]       = *reinterpret_cast<unsigned short*>(&h2);
                T[(n + 1) * 144 + mA + 8] = *reinterpret_cast<unsigned short*>(&h3);
            }
        }
        __syncthreads();
        #pragma unroll
        for (int i = 0; i < 8; i++) {
            int cc = tid + i * 256;
            int row = cc >> 4, cq = cc & 15;
            uint4 v = *reinterpret_cast<const uint4*>(T + row * 144 + cq * 8);
            size_t o = ((size_t)b * HW + n0 + row) * (size_t)M + m0 + cq * 8;
            *reinterpret_cast<uint4*>(OutH + o) = v;
        }
    } else {
        const bool doexp = (EPI == 5) && (m0 < 1024);
        const int mrow = m0 + wm * 32 + (lane >> 2);
        const int ncol = n0 + wn * 64 + (lane & 3) * 2;
        float ls = 0.f, lq = 0.f;
        #pragma unroll
        for (int mi = 0; mi < 2; mi++) {
            const int mA = mrow + mi * 16;
            const float bv0 = __ldg(bias + mA);
            const float bv1 = __ldg(bias + mA + 8);
            #pragma unroll
            for (int nf = 0; nf < 8; nf++) {
                const int n = ncol + nf * 8;
                size_t iA = ((size_t)b * M + mA) * HW + n;
                size_t iB = iA + (size_t)8 * HW;
                float2 v0 = make_float2(acc[mi][nf][0] + bv0, acc[mi][nf][1] + bv0);
                float2 v1 = make_float2(acc[mi][nf][2] + bv1, acc[mi][nf][3] + bv1);
                if (EPI == 5) {
                    if (doexp) {
                        v0.x = fexp(v0.x); v0.y = fexp(v0.y);
                        v1.x = fexp(v1.x); v1.y = fexp(v1.y);
                    }
                } else if (EPI == 1) {
                    float2 a0 = *reinterpret_cast<const float2*>(aux + iA);
                    float2 a1 = *reinterpret_cast<const float2*>(aux + iB);
                    v0.x += a0.x; v0.y += a0.y; v1.x += a1.x; v1.y += a1.y;
                    ls += v0.x + v0.y + v1.x + v1.y;
                    lq += v0.x * v0.x + v0.y * v0.y + v1.x * v1.x + v1.y * v1.y;
                } else if (EPI == 3) {
                    float2 a0 = *reinterpret_cast<const float2*>(Out + iA);
                    float2 a1 = *reinterpret_cast<const float2*>(Out + iB);
                    v0.x += a0.x; v0.y += a0.y; v1.x += a1.x; v1.y += a1.y;
                }
                *reinterpret_cast<float2*>(Out + iA) = v0;
                *reinterpret_cast<float2*>(Out + iB) = v1;
            }
        }
        if (EPI == 1) {
            ls = bred_sum(ls);
            lq = bred_sum(lq);
            if (tid == 0)
                part[b * 128 + blockIdx.y * 32 + blockIdx.x] = make_float2(ls, lq);
        }
    }
}

// ===== qsum: per-pixel sum over 512 channels of expQ; QKV layout (b,1536,HW) =====
__global__ __launch_bounds__(256) void colsum(const float* __restrict__ QKV,
                                              float* __restrict__ qsum) {
    int gid = blockIdx.x * 256 + threadIdx.x;
    int b = gid >> 12, pix = gid & 4095;
    const float* base = QKV + (size_t)b * 3 * PERB + pix;
    float s = 0.f;
    for (int c = 0; c < CCH; c++) s += base[(size_t)c * HW];
    qsum[gid] = s;
}

// ===== kinv: 1/rowsum of expK =====
__global__ __launch_bounds__(256) void rowsum_inv(const float* __restrict__ QKV,
                                                  float* __restrict__ kinv) {
    const int bx = blockIdx.x;                       // b*512 + c
    const float* row = QKV + (size_t)(bx >> 9) * 3 * PERB + PERB + (size_t)(bx & 511) * HW;
    float s = 0.f;
    #pragma unroll
    for (int i = 0; i < 4; i++) {
        float4 v = reinterpret_cast<const float4*>(row)[threadIdx.x + i * 256];
        s += v.x + v.y + v.z + v.w;
    }
    s = bred_sum(s);
    if (threadIdx.x == 0) kinv[bx] = 1.f / s;
}

// ================= attention =================
// split-K partial: KVp[cx][bh][k][v] = sum_{p in chunk cx} expK[k,p]*V[v,p]
__global__ __launch_bounds__(256) void kv_part(const float* __restrict__ QKV,
                                               float* __restrict__ KVp) {
    const int cx = blockIdx.x;       // 0..7
    const int bh = blockIdx.y;       // 0..127
    const int b = bh >> 3, h = bh & 7;
    const float* Kb = QKV + (size_t)b * 3 * PERB + PERB     + (size_t)h * HDIM * HW;
    const float* Vb = QKV + (size_t)b * 3 * PERB + 2 * PERB + (size_t)h * HDIM * HW;
    __shared__ float Ks[64][65];
    __shared__ float Vs[64][65];
    const int tid = threadIdx.x;
    const int tx = tid & 15, ty = tid >> 4;
    float acc[4][4] = {};
    const int pbeg = cx * 512, pend = pbeg + 512;
    for (int p0 = pbeg; p0 < pend; p0 += 64) {
        #pragma unroll
        for (int t = 0; t < 4; t++) {
            int lin = tid + t * 256;
            int r = lin >> 4, c4 = (lin & 15) * 4;
            float4 kv4 = *reinterpret_cast<const float4*>(&Kb[(size_t)r * HW + p0 + c4]);
            float4 vv4 = *reinterpret_cast<const float4*>(&Vb[(size_t)r * HW + p0 + c4]);
            Ks[r][c4 + 0] = kv4.x; Ks[r][c4 + 1] = kv4.y; Ks[r][c4 + 2] = kv4.z; Ks[r][c4 + 3] = kv4.w;
            Vs[r][c4 + 0] = vv4.x; Vs[r][c4 + 1] = vv4.y; Vs[r][c4 + 2] = vv4.z; Vs[r][c4 + 3] = vv4.w;
        }
        __syncthreads();
        #pragma unroll 8
        for (int p = 0; p < 64; p++) {
            float ra[4], rb[4];
            #pragma unroll
            for (int i = 0; i < 4; i++) ra[i] = Ks[ty * 4 + i][p];
            #pragma unroll
            for (int j = 0; j < 4; j++) rb[j] = Vs[tx * 4 + j][p];
            #pragma unroll
            for (int i = 0; i < 4; i++)
                #pragma unroll
                for (int j = 0; j < 4; j++)
                    acc[i][j] = fmaf(ra[i], rb[j], acc[i][j]);
        }
        __syncthreads();
    }
    float* out = KVp + ((size_t)cx * 128 + bh) * (HDIM * HDIM);
    #pragma unroll
    for (int i = 0; i < 4; i++)
        #pragma unroll
        for (int j = 0; j < 4; j++)
            out[(ty * 4 + i) * HDIM + tx * 4 + j] = acc[i][j];
}
// deterministic reduce over 8 chunks, apply kinv
__global__ __launch_bounds__(256) void kv_reduce(const float* __restrict__ KVp,
                                                 const float* __restrict__ kinv,
                                                 float* __restrict__ KV) {
    const int bh = blockIdx.x;
    const int b = bh >> 3, h = bh & 7;
    #pragma unroll
    for (int t = 0; t < 16; t++) {
        int e = threadIdx.x + t * 256;   // 0..4095
        float s = 0.f;
        #pragma unroll
        for (int cx = 0; cx < 8; cx++)
            s += KVp[((size_t)cx * 128 + bh) * (HDIM * HDIM) + e];
        int k = e >> 6;
        KV[(size_t)bh * HDIM * HDIM + e] = s * __ldg(kinv + b * CCH + h * HDIM + k);
    }
}
// attn -> fp16 pixel-major Th
__global__ __launch_bounds__(256) void attn_kernel(const float* __restrict__ KV,
                                                   const float* __restrict__ QKV,
                                                   const float* __restrict__ qsum,
                                                   __half* __restrict__ Th) {
    const int bh = blockIdx.y;
    const int p0 = blockIdx.x * 64;
    const int b = bh >> 3, h = bh & 7;
    const float* Qb  = QKV + (size_t)b * 3 * PERB + (size_t)h * HDIM * HW;
    const float* KVb = KV + (size_t)bh * HDIM * HDIM;
    __shared__ float KVs[64][64];
    __shared__ float Qs[64][68];
    __shared__ unsigned short TT[64][72];
    const int tid = threadIdx.x;
    const int tx = tid & 15, ty = tid >> 4;
    #pragma unroll
    for (int t = 0; t < 4; t++) {
        int lin = tid + t * 256;
        int r = lin >> 4, c4 = (lin & 15) * 4;
        *reinterpret_cast<float4*>(&KVs[r][c4]) =
            *reinterpret_cast<const float4*>(&KVb[(size_t)r * HDIM + c4]);
        float4 q4 = *reinterpret_cast<const float4*>(&Qb[(size_t)r * HW + p0 + c4]);
        *reinterpret_cast<float4*>(&Qs[r][c4]) = q4;
    }
    __syncthreads();
    float acc[4][4] = {};
    #pragma unroll 8
    for (int k = 0; k < 64; k++) {
        float4 q4 = *reinterpret_cast<const float4*>(&Qs[k][tx * 4]);
        float4 a4 = *reinterpret_cast<const float4*>(&KVs[k][ty * 4]);
        float ra[4] = {a4.x, a4.y, a4.z, a4.w};
        float rb[4] = {q4.x, q4.y, q4.z, q4.w};
        #pragma unroll
        for (int i = 0; i < 4; i++)
            #pragma unroll
            for (int j = 0; j < 4; j++)
                acc[i][j] = fmaf(ra[i], rb[j], acc[i][j]);
    }
    const int bq = b * HW + p0 + tx * 4;
    float inv[4];
    #pragma unroll
    for (int j = 0; j < 4; j++) inv[j] = 1.f / qsum[bq + j];
    #pragma unroll
    for (int i = 0; i < 4; i++)
        #pragma unroll
        for (int j = 0; j < 4; j++) {
            __half hv = __float2half_rn(acc[i][j] * inv[j]);
            TT[tx * 4 + j][ty * 4 + i] = *reinterpret_cast<unsigned short*>(&hv);
        }
    __syncthreads();
    #pragma unroll
    for (int t = 0; t < 2; t++) {
        int cc = tid + t * 256;
        int p = cc >> 3, co = (cc & 7) * 8;
        uint4 v = *reinterpret_cast<const uint4*>(&TT[p][co]);
        size_t o = ((size_t)b * HW + p0 + p) * CCH + h * 64 + co;
        *reinterpret_cast<uint4*>(Th + o) = v;
    }
}

// ================= launch =================
extern "C" void kernel_launch(void* const* d_in, const int* in_sizes, int n_in,
                              void* d_out, int out_size) {
    const float* x     = (const float*)d_in[0];
    const float* ln1w  = (const float*)d_in[1];
    const float* ln1b  = (const float*)d_in[2];
    const float* qw    = (const float*)d_in[3];
    const float* qb    = (const float*)d_in[4];
    const float* kw    = (const float*)d_in[5];
    const float* kb    = (const float*)d_in[6];
    const float* vw    = (const float*)d_in[7];
    const float* vb    = (const float*)d_in[8];
    const float* huw   = (const float*)d_in[9];
    const float* hub   = (const float*)d_in[10];
    const float* ln2w  = (const float*)d_in[11];
    const float* ln2b  = (const float*)d_in[12];
    const float* ff1w  = (const float*)d_in[13];
    const float* ff1b  = (const float*)d_in[14];
    const float* ff2w  = (const float*)d_in[15];
    const float* ff2b  = (const float*)d_in[16];
    float* out = (float*)d_out;

    float *QKV, *R, *KVp, *KV, *qsum, *kinv, *bqkv;
    float2 *part, *stats;
    __half *Th, *Fh, *Wh;
    cudaGetSymbolAddress((void**)&QKV, g_QKV);
    cudaGetSymbolAddress((void**)&R, g_R);
    cudaGetSymbolAddress((void**)&KVp, g_KVp);
    cudaGetSymbolAddress((void**)&KV, g_KV);
    cudaGetSymbolAddress((void**)&qsum, g_qsum);
    cudaGetSymbolAddress((void**)&kinv, g_kinv);
    cudaGetSymbolAddress((void**)&bqkv, g_bqkv);
    cudaGetSymbolAddress((void**)&part, g_part);
    cudaGetSymbolAddress((void**)&stats, g_stats);
    cudaGetSymbolAddress((void**)&Th, g_Th);
    cudaGetSymbolAddress((void**)&Fh, g_Fh);
    cudaGetSymbolAddress((void**)&Wh, g_Wh);

    const int SMEM = 4 * GSTAGE;   // 81920
    cudaFuncSetAttribute(hmma_gemm<1>, cudaFuncAttributeMaxDynamicSharedMemorySize, SMEM);
    cudaFuncSetAttribute(hmma_gemm<2>, cudaFuncAttributeMaxDynamicSharedMemorySize, SMEM);
    cudaFuncSetAttribute(hmma_gemm<3>, cudaFuncAttributeMaxDynamicSharedMemorySize, SMEM);
    cudaFuncSetAttribute(hmma_gemm<5>, cudaFuncAttributeMaxDynamicSharedMemorySize, SMEM);

    const dim3 gT(HW / 32, CCH / 32, BATCH);         // (128, 16, 16)
    const dim3 gQKVg(HW / 128, 1536 / 128, BATCH);   // (32, 12, 16)
    const dim3 gG512(HW / 128, CCH / 128, BATCH);    // (32, 4, 16)
    const dim3 gG2048(HW / 128, DHID / 128, BATCH);  // (32, 16, 16)

    // 1-2: weight conversion + bias pack
    wconv_all<<<WTOT / 256, 256>>>(qw, kw, vw, huw, ff1w, ff2w, Wh);
    pack_bias<<<2, 768>>>(qb, kb, vb, bqkv);

    // 3-5: ln1 -> Th
    ln_stats<<<dim3(128, BATCH), 256>>>(x, part);
    ln_finalize<<<1, 32>>>(part, stats);
    conv_t<1, 0><<<gT, 256>>>(x, ln1w, ln1b, stats, Th, nullptr);

    // 6: fused QKV GEMM (launch #6 -> ncu capture target)
    hmma_gemm<5><<<gQKVg, 256, SMEM>>>(Wh, Th, bqkv, nullptr, QKV, nullptr, nullptr, CCH, 1536);

    colsum<<<(BATCH * HW) / 256, 256>>>(QKV, qsum);
    rowsum_inv<<<BATCH * CCH, 256>>>(QKV, kinv);

    kv_part<<<dim3(8, 128), 256>>>(QKV, KVp);
    kv_reduce<<<128, 256>>>(KVp, kinv, KV);
    attn_kernel<<<dim3(HW / 64, BATCH * NHEAD), 256>>>(KV, QKV, qsum, Th);  // -> Th fp16

    // R = x + hu(attn); LN2 partials fused
    hmma_gemm<1><<<gG512, 256, SMEM>>>(Wh + WOFF_HU, Th, hub, x, R, nullptr, part, CCH, CCH);
    ln_finalize<<<1, 32>>>(part, stats);

    // ln2 fused: out (fp32) + Th (fp16 pixel-major)
    conv_t<1, 1><<<gT, 256>>>(R, ln2w, ln2b, stats, Th, out);

    // Fh = fp16(gelu(ff1)); out += ff2(Fh)
    hmma_gemm<2><<<gG2048, 256, SMEM>>>(Wh + WOFF_FF1, Th, ff1b, nullptr, nullptr, Fh, nullptr, CCH, DHID);
    hmma_gemm<3><<<gG512, 256, SMEM>>>(Wh + WOFF_FF2, Fh, ff2b, nullptr, out, nullptr, nullptr, DHID, CCH);
}

// round 9
// speedup vs baseline: 4.8758x; 1.1259x over previous
#include <cuda_runtime.h>
#include <cuda_fp16.h>
#include <math.h>
#include <stdint.h>

// ---------------- problem constants ----------------
#define BATCH 16
#define CCH   512
#define HW    4096
#define DHID  2048
#define NHEAD 8
#define HDIM  64
#define PERB  (CCH*HW)
#define LN_EPS 1e-5f

// ---------------- device scratch (allocation-free) ----------------
__device__ float g_QKV[(size_t)BATCH*3*PERB];   // expQ/expK/V per batch: (b, 1536, HW)
__device__ float g_R  [BATCH*PERB];             // residual R = x + hu(attn)
__device__ float g_KVp[8*128*HDIM*HDIM];        // split-K partials
__device__ float g_KV [BATCH*NHEAD*HDIM*HDIM];
__device__ float g_qsum[BATCH*HW];
__device__ float g_kinv[BATCH*CCH];
__device__ float g_bqkv[3*CCH];
__device__ float2 g_part[BATCH*128];
__device__ float2 g_stats[BATCH];
// fp16 activations pixel-major (b, p, c)
__device__ __half g_Th[(size_t)BATCH*HW*CCH];
__device__ __half g_Fh[(size_t)BATCH*HW*DHID];
// fp16 weights (stacked: q,k,v,hu,ff1,ff2)
#define WOFF_HU  786432
#define WOFF_FF1 1048576
#define WOFF_FF2 2097152
#define WTOT     3145728
__device__ __half g_Wh[WTOT];

// ================= PTX helpers =================
__device__ __forceinline__ uint32_t smem_u32(const void* p) {
    uint32_t a;
    asm("{ .reg .u64 t; cvta.to.shared.u64 t, %1; cvt.u32.u64 %0, t; }" : "=r"(a) : "l"(p));
    return a;
}
__device__ __forceinline__ void cp16(uint32_t dst, const void* src) {
    asm volatile("cp.async.cg.shared.global [%0], [%1], 16;" :: "r"(dst), "l"(src));
}
__device__ __forceinline__ void cp_commit() {
    asm volatile("cp.async.commit_group;" ::: "memory");
}
template <int N>
__device__ __forceinline__ void cp_wait() {
    asm volatile("cp.async.wait_group %0;" :: "n"(N) : "memory");
}
__device__ __forceinline__ void ldm_x4(uint32_t* r, uint32_t addr) {
    asm volatile("ldmatrix.sync.aligned.m8n8.x4.shared.b16 {%0,%1,%2,%3}, [%4];"
                 : "=r"(r[0]), "=r"(r[1]), "=r"(r[2]), "=r"(r[3]) : "r"(addr));
}
__device__ __forceinline__ void mma_f16(float* c, const uint32_t* a, const uint32_t* b) {
    asm("mma.sync.aligned.m16n8k16.row.col.f32.f16.f16.f32 "
        "{%0,%1,%2,%3}, {%4,%5,%6,%7}, {%8,%9}, {%0,%1,%2,%3};"
        : "+f"(c[0]), "+f"(c[1]), "+f"(c[2]), "+f"(c[3])
        : "r"(a[0]), "r"(a[1]), "r"(a[2]), "r"(a[3]), "r"(b[0]), "r"(b[1]));
}

// fast exp on FMA pipe
__device__ __forceinline__ float fexp(float x) {
    float t = x * 1.4426950408889634f;
    float n = rintf(t);
    float r = t - n;
    float p = 0.00015403530393381609f;
    p = fmaf(p, r, 0.0013333558146428443f);
    p = fmaf(p, r, 0.009618129107628477f);
    p = fmaf(p, r, 0.05550410866482158f);
    p = fmaf(p, r, 0.2402265069591007f);
    p = fmaf(p, r, 0.6931471805599453f);
    p = fmaf(p, r, 1.0f);
    int e = __float2int_rn(n);
    return p * __int_as_float((e + 127) << 23);
}

// ================= block reductions =================
__device__ __forceinline__ float bred_sum(float v) {
    __shared__ float sb[8];
    int lane = threadIdx.x & 31, w = threadIdx.x >> 5;
    #pragma unroll
    for (int o = 16; o; o >>= 1) v += __shfl_down_sync(0xffffffffu, v, o);
    if (lane == 0) sb[w] = v;
    __syncthreads();
    if (threadIdx.x < 32) {
        float r = (lane < 8) ? sb[lane] : 0.f;
        #pragma unroll
        for (int o = 4; o; o >>= 1) r += __shfl_down_sync(0xffffffffu, r, o);
        if (lane == 0) sb[0] = r;
    }
    __syncthreads();
    float out = sb[0];
    __syncthreads();
    return out;
}

// ================= weight conversion =================
__global__ __launch_bounds__(256) void wconv_all(const float* __restrict__ qw,
                                                 const float* __restrict__ kw,
                                                 const float* __restrict__ vw,
                                                 const float* __restrict__ huw,
                                                 const float* __restrict__ ff1w,
                                                 const float* __restrict__ ff2w,
                                                 __half* __restrict__ h) {
    int i = blockIdx.x * 256 + threadIdx.x;
    float v;
    if (i < 786432) {
        int seg = i >> 18, off = i & 262143;
        v = (seg == 0) ? qw[off] : (seg == 1) ? kw[off] : vw[off];
    } else if (i < 1048576) {
        v = huw[i - 786432];
    } else if (i < 2097152) {
        v = ff1w[i - 1048576];
    } else {
        v = ff2w[i - 2097152];
    }
    h[i] = __float2half_rn(v);
}
__global__ void pack_bias(const float* __restrict__ qb, const float* __restrict__ kb,
                          const float* __restrict__ vb, float* __restrict__ bq) {
    int i = blockIdx.x * 768 + threadIdx.x;
    if (i < 512) bq[i] = qb[i];
    else if (i < 1024) bq[i] = kb[i - 512];
    else if (i < 1536) bq[i] = vb[i - 1024];
}

// ================= LayerNorm stats =================
__global__ __launch_bounds__(256) void ln_stats(const float* __restrict__ in,
                                                float2* __restrict__ part) {
    int b = blockIdx.y, pb = blockIdx.x;
    const float* p = in + (size_t)b * PERB + (size_t)pb * 16384;
    float s = 0.f, q = 0.f;
    #pragma unroll
    for (int i = 0; i < 16; i++) {
        float4 v = *reinterpret_cast<const float4*>(p + (size_t)(threadIdx.x + i * 256) * 4);
        s += v.x + v.y + v.z + v.w;
        q += v.x * v.x + v.y * v.y + v.z * v.z + v.w * v.w;
    }
    s = bred_sum(s);
    q = bred_sum(q);
    if (threadIdx.x == 0) part[b * 128 + pb] = make_float2(s, q);
}
// parallel finalize: one block per batch, 128 threads, deterministic tree reduce
__global__ __launch_bounds__(128) void ln_finalize(const float2* __restrict__ part,
                                                   float2* __restrict__ stats) {
    __shared__ double ss[128], qq[128];
    const int b = blockIdx.x, t = threadIdx.x;
    float2 p = part[b * 128 + t];
    ss[t] = (double)p.x;
    qq[t] = (double)p.y;
    __syncthreads();
    #pragma unroll
    for (int o = 64; o; o >>= 1) {
        if (t < o) { ss[t] += ss[t + o]; qq[t] += qq[t + o]; }
        __syncthreads();
    }
    if (t == 0) {
        double invN = 1.0 / (double)PERB;
        double mu = ss[0] * invN;
        double var = qq[0] * invN - mu * mu;
        double rstd = 1.0 / sqrt(var + (double)LN_EPS);
        stats[b] = make_float2((float)mu, (float)rstd);
    }
}

// ===== activation convert+transpose: fp32 (b,512,HW) -> fp16 (b,HW,512) =====
template <int DO_LN, int DO_OUT>
__global__ __launch_bounds__(256) void conv_t(const float* __restrict__ in,
                                              const float* __restrict__ lnw,
                                              const float* __restrict__ lnb,
                                              const float2* __restrict__ stats,
                                              __half* __restrict__ oh,
                                              float* __restrict__ out32) {
    __shared__ float T[32][33];
    const int p0 = blockIdx.x * 32, c0 = blockIdx.y * 32, b = blockIdx.z;
    const int t = threadIdx.x;
    {
        int cl = t >> 3, p4 = (t & 7) * 4;
        size_t gidx = ((size_t)b * CCH + c0 + cl) * HW + p0 + p4;
        float4 v = *reinterpret_cast<const float4*>(in + gidx);
        if (DO_LN) {
            float2 st = stats[b];
            size_t widx = (size_t)(c0 + cl) * HW + p0 + p4;
            float4 wv = *reinterpret_cast<const float4*>(lnw + widx);
            float4 bv = *reinterpret_cast<const float4*>(lnb + widx);
            v.x = (v.x - st.x) * st.y * wv.x + bv.x;
            v.y = (v.y - st.x) * st.y * wv.y + bv.y;
            v.z = (v.z - st.x) * st.y * wv.z + bv.z;
            v.w = (v.w - st.x) * st.y * wv.w + bv.w;
        }
        if (DO_OUT) *reinterpret_cast<float4*>(out32 + gidx) = v;
        T[cl][p4 + 0] = v.x; T[cl][p4 + 1] = v.y; T[cl][p4 + 2] = v.z; T[cl][p4 + 3] = v.w;
    }
    __syncthreads();
    {
        int pl = t >> 3, c4 = (t & 7) * 4;
        unsigned short hb[4];
        #pragma unroll
        for (int j = 0; j < 4; j++) {
            __half hv = __float2half_rn(T[c4 + j][pl]);
            hb[j] = *reinterpret_cast<unsigned short*>(&hv);
        }
        uint2 pk;
        pk.x = (unsigned int)hb[0] | ((unsigned int)hb[1] << 16);
        pk.y = (unsigned int)hb[2] | ((unsigned int)hb[3] << 16);
        size_t o = ((size_t)b * HW + p0 + pl) * CCH + c0 + c4;
        *reinterpret_cast<uint2*>(oh + o) = pk;
    }
}

// ================= HMMA fp16 GEMM (mma.sync, cp.async 4-stage, 2 CTA/SM) =================
// EPI 1: +bias+aux -> fp32, + LN partial sums    EPI 2: gelu(+bias) -> fp16 pixel-major
// EPI 3: +bias accumulate into Out               EPI 5: exp(+bias) if m0<1024 else +bias (QKV)
#define GSTAGE 20480
template <int EPI>
__global__ __launch_bounds__(256, 2)
void hmma_gemm(const __half* __restrict__ wh,
               const __half* __restrict__ ah,
               const float* __restrict__ bias, const float* __restrict__ aux,
               float* __restrict__ Out, __half* __restrict__ OutH,
               float2* __restrict__ part, int K, int M) {
    extern __shared__ unsigned char smem_raw[];
    const uint32_t sb0 = smem_u32(smem_raw);

    const int tid = threadIdx.x;
    const int lane = tid & 31, wid = tid >> 5;
    const int wm = wid & 3, wn = wid >> 2;
    const int n0 = blockIdx.x * 128, m0 = blockIdx.y * 128, b = blockIdx.z;

    const __half* A0 = wh + (size_t)m0 * K;
    const __half* B0 = ah + ((size_t)b * HW + n0) * K;

    const int r0 = tid >> 2, c0c = tid & 3;
    const int r1 = (tid + 256) >> 2;
    const uint32_t s0 = (uint32_t)(r0 * 80 + c0c * 16);
    const uint32_t s1 = (uint32_t)(r1 * 80 + c0c * 16);
    const size_t g0 = (size_t)r0 * K + c0c * 8;
    const size_t g1 = (size_t)r1 * K + c0c * 8;

    const uint32_t aoff = (uint32_t)((wm * 32 + (lane & 15)) * 80 + (lane >> 4) * 16);
    const uint32_t boff = (uint32_t)(10240 +
        (wn * 64 + (lane & 7) + ((lane >> 4) << 3)) * 80 + ((lane >> 3) & 1) * 16);

    float acc[2][8][4];
    #pragma unroll
    for (int i = 0; i < 2; i++)
        #pragma unroll
        for (int j = 0; j < 8; j++)
            #pragma unroll
            for (int q = 0; q < 4; q++) acc[i][j][q] = 0.f;

    const int NIT = K >> 5;

    #pragma unroll
    for (int s = 0; s < 3; s++) {
        uint32_t sbs = sb0 + s * GSTAGE;
        size_t k0 = (size_t)s * 32;
        cp16(sbs + s0,         A0 + g0 + k0);  cp16(sbs + s1,         A0 + g1 + k0);
        cp16(sbs + 10240 + s0, B0 + g0 + k0);  cp16(sbs + 10240 + s1, B0 + g1 + k0);
        cp_commit();
    }

    for (int it = 0; it < NIT; it++) {
        cp_wait<2>();
        __syncthreads();

        if (it + 3 < NIT) {
            int ls = (it + 3) & 3;
            uint32_t sbs = sb0 + ls * GSTAGE;
            size_t k0 = (size_t)(it + 3) * 32;
            cp16(sbs + s0,         A0 + g0 + k0);  cp16(sbs + s1,         A0 + g1 + k0);
            cp16(sbs + 10240 + s0, B0 + g0 + k0);  cp16(sbs + 10240 + s1, B0 + g1 + k0);
        }
        cp_commit();

        const uint32_t sbs = sb0 + (it & 3) * GSTAGE;
        #pragma unroll
        for (int kk = 0; kk < 2; kk++) {
            const uint32_t kb = kk * 32;
            uint32_t ra[2][4], rb[4][4];
            #pragma unroll
            for (int mi = 0; mi < 2; mi++)
                ldm_x4(ra[mi], sbs + aoff + mi * 1280 + kb);
            #pragma unroll
            for (int ni = 0; ni < 4; ni++)
                ldm_x4(rb[ni], sbs + boff + ni * 1280 + kb);
            #pragma unroll
            for (int mi = 0; mi < 2; mi++)
                #pragma unroll
                for (int ni = 0; ni < 4; ni++)
                    #pragma unroll
                    for (int j = 0; j < 2; j++)
                        mma_f16(acc[mi][ni * 2 + j], ra[mi], &rb[ni][j * 2]);
        }
    }

    if (EPI == 2) {
        cp_wait<0>();
        __syncthreads();
        unsigned short* T = reinterpret_cast<unsigned short*>(smem_raw);   // [128][144]
        const int lm0 = wm * 32 + (lane >> 2);
        const int ln0 = wn * 64 + (lane & 3) * 2;
        #pragma unroll
        for (int mi = 0; mi < 2; mi++) {
            const int mA = lm0 + mi * 16;
            const float bv0 = __ldg(bias + m0 + mA);
            const float bv1 = __ldg(bias + m0 + mA + 8);
            #pragma unroll
            for (int nf = 0; nf < 8; nf++) {
                const int n = ln0 + nf * 8;
                float v0 = acc[mi][nf][0] + bv0;
                float v1 = acc[mi][nf][1] + bv0;
                float v2 = acc[mi][nf][2] + bv1;
                float v3 = acc[mi][nf][3] + bv1;
                v0 = 0.5f * v0 * (1.0f + erff(v0 * 0.70710678118654752f));
                v1 = 0.5f * v1 * (1.0f + erff(v1 * 0.70710678118654752f));
                v2 = 0.5f * v2 * (1.0f + erff(v2 * 0.70710678118654752f));
                v3 = 0.5f * v3 * (1.0f + erff(v3 * 0.70710678118654752f));
                __half h0 = __float2half_rn(v0), h1 = __float2half_rn(v1);
                __half h2 = __float2half_rn(v2), h3 = __float2half_rn(v3);
                T[n * 144 + mA]           = *reinterpret_cast<unsigned short*>(&h0);
                T[(n + 1) * 144 + mA]     = *reinterpret_cast<unsigned short*>(&h1);
                T[n * 144 + mA + 8]       = *reinterpret_cast<unsigned short*>(&h2);
                T[(n + 1) * 144 + mA + 8] = *reinterpret_cast<unsigned short*>(&h3);
            }
        }
        __syncthreads();
        #pragma unroll
        for (int i = 0; i < 8; i++) {
            int cc = tid + i * 256;
            int row = cc >> 4, cq = cc & 15;
            uint4 v = *reinterpret_cast<const uint4*>(T + row * 144 + cq * 8);
            size_t o = ((size_t)b * HW + n0 + row) * (size_t)M + m0 + cq * 8;
            *reinterpret_cast<uint4*>(OutH + o) = v;
        }
    } else {
        const bool doexp = (EPI == 5) && (m0 < 1024);
        const int mrow = m0 + wm * 32 + (lane >> 2);
        const int ncol = n0 + wn * 64 + (lane & 3) * 2;
        float ls = 0.f, lq = 0.f;
        #pragma unroll
        for (int mi = 0; mi < 2; mi++) {
            const int mA = mrow + mi * 16;
            const float bv0 = __ldg(bias + mA);
            const float bv1 = __ldg(bias + mA + 8);
            #pragma unroll
            for (int nf = 0; nf < 8; nf++) {
                const int n = ncol + nf * 8;
                size_t iA = ((size_t)b * M + mA) * HW + n;
                size_t iB = iA + (size_t)8 * HW;
                float2 v0 = make_float2(acc[mi][nf][0] + bv0, acc[mi][nf][1] + bv0);
                float2 v1 = make_float2(acc[mi][nf][2] + bv1, acc[mi][nf][3] + bv1);
                if (EPI == 5) {
                    if (doexp) {
                        v0.x = fexp(v0.x); v0.y = fexp(v0.y);
                        v1.x = fexp(v1.x); v1.y = fexp(v1.y);
                    }
                } else if (EPI == 1) {
                    float2 a0 = *reinterpret_cast<const float2*>(aux + iA);
                    float2 a1 = *reinterpret_cast<const float2*>(aux + iB);
                    v0.x += a0.x; v0.y += a0.y; v1.x += a1.x; v1.y += a1.y;
                    ls += v0.x + v0.y + v1.x + v1.y;
                    lq += v0.x * v0.x + v0.y * v0.y + v1.x * v1.x + v1.y * v1.y;
                } else if (EPI == 3) {
                    float2 a0 = *reinterpret_cast<const float2*>(Out + iA);
                    float2 a1 = *reinterpret_cast<const float2*>(Out + iB);
                    v0.x += a0.x; v0.y += a0.y; v1.x += a1.x; v1.y += a1.y;
                }
                *reinterpret_cast<float2*>(Out + iA) = v0;
                *reinterpret_cast<float2*>(Out + iB) = v1;
            }
        }
        if (EPI == 1) {
            ls = bred_sum(ls);
            lq = bred_sum(lq);
            if (tid == 0)
                part[b * 128 + blockIdx.y * 32 + blockIdx.x] = make_float2(ls, lq);
        }
    }
}

// ===== qsum: per-pixel sum over 512 channels of expQ =====
__global__ __launch_bounds__(256) void colsum(const float* __restrict__ QKV,
                                              float* __restrict__ qsum) {
    int gid = blockIdx.x * 256 + threadIdx.x;
    int b = gid >> 12, pix = gid & 4095;
    const float* base = QKV + (size_t)b * 3 * PERB + pix;
    float s = 0.f;
    for (int c = 0; c < CCH; c++) s += base[(size_t)c * HW];
    qsum[gid] = s;
}

// ===== kinv: 1/rowsum of expK =====
__global__ __launch_bounds__(256) void rowsum_inv(const float* __restrict__ QKV,
                                                  float* __restrict__ kinv) {
    const int bx = blockIdx.x;
    const float* row = QKV + (size_t)(bx >> 9) * 3 * PERB + PERB + (size_t)(bx & 511) * HW;
    float s = 0.f;
    #pragma unroll
    for (int i = 0; i < 4; i++) {
        float4 v = reinterpret_cast<const float4*>(row)[threadIdx.x + i * 256];
        s += v.x + v.y + v.z + v.w;
    }
    s = bred_sum(s);
    if (threadIdx.x == 0) kinv[bx] = 1.f / s;
}

// ================= attention =================
__global__ __launch_bounds__(256) void kv_part(const float* __restrict__ QKV,
                                               float* __restrict__ KVp) {
    const int cx = blockIdx.x;
    const int bh = blockIdx.y;
    const int b = bh >> 3, h = bh & 7;
    const float* Kb = QKV + (size_t)b * 3 * PERB + PERB     + (size_t)h * HDIM * HW;
    const float* Vb = QKV + (size_t)b * 3 * PERB + 2 * PERB + (size_t)h * HDIM * HW;
    __shared__ float Ks[64][65];
    __shared__ float Vs[64][65];
    const int tid = threadIdx.x;
    const int tx = tid & 15, ty = tid >> 4;
    float acc[4][4] = {};
    const int pbeg = cx * 512, pend = pbeg + 512;
    for (int p0 = pbeg; p0 < pend; p0 += 64) {
        #pragma unroll
        for (int t = 0; t < 4; t++) {
            int lin = tid + t * 256;
            int r = lin >> 4, c4 = (lin & 15) * 4;
            float4 kv4 = *reinterpret_cast<const float4*>(&Kb[(size_t)r * HW + p0 + c4]);
            float4 vv4 = *reinterpret_cast<const float4*>(&Vb[(size_t)r * HW + p0 + c4]);
            Ks[r][c4 + 0] = kv4.x; Ks[r][c4 + 1] = kv4.y; Ks[r][c4 + 2] = kv4.z; Ks[r][c4 + 3] = kv4.w;
            Vs[r][c4 + 0] = vv4.x; Vs[r][c4 + 1] = vv4.y; Vs[r][c4 + 2] = vv4.z; Vs[r][c4 + 3] = vv4.w;
        }
        __syncthreads();
        #pragma unroll 8
        for (int p = 0; p < 64; p++) {
            float ra[4], rb[4];
            #pragma unroll
            for (int i = 0; i < 4; i++) ra[i] = Ks[ty * 4 + i][p];
            #pragma unroll
            for (int j = 0; j < 4; j++) rb[j] = Vs[tx * 4 + j][p];
            #pragma unroll
            for (int i = 0; i < 4; i++)
                #pragma unroll
                for (int j = 0; j < 4; j++)
                    acc[i][j] = fmaf(ra[i], rb[j], acc[i][j]);
        }
        __syncthreads();
    }
    float* out = KVp + ((size_t)cx * 128 + bh) * (HDIM * HDIM);
    #pragma unroll
    for (int i = 0; i < 4; i++)
        #pragma unroll
        for (int j = 0; j < 4; j++)
            out[(ty * 4 + i) * HDIM + tx * 4 + j] = acc[i][j];
}
__global__ __launch_bounds__(256) void kv_reduce(const float* __restrict__ KVp,
                                                 const float* __restrict__ kinv,
                                                 float* __restrict__ KV) {
    const int bh = blockIdx.x;
    const int b = bh >> 3, h = bh & 7;
    #pragma unroll
    for (int t = 0; t < 16; t++) {
        int e = threadIdx.x + t * 256;
        float s = 0.f;
        #pragma unroll
        for (int cx = 0; cx < 8; cx++)
            s += KVp[((size_t)cx * 128 + bh) * (HDIM * HDIM) + e];
        int k = e >> 6;
        KV[(size_t)bh * HDIM * HDIM + e] = s * __ldg(kinv + b * CCH + h * HDIM + k);
    }
}
__global__ __launch_bounds__(256) void attn_kernel(const float* __restrict__ KV,
                                                   const float* __restrict__ QKV,
                                                   const float* __restrict__ qsum,
                                                   __half* __restrict__ Th) {
    const int bh = blockIdx.y;
    const int p0 = blockIdx.x * 64;
    const int b = bh >> 3, h = bh & 7;
    const float* Qb  = QKV + (size_t)b * 3 * PERB + (size_t)h * HDIM * HW;
    const float* KVb = KV + (size_t)bh * HDIM * HDIM;
    __shared__ float KVs[64][64];
    __shared__ float Qs[64][68];
    __shared__ unsigned short TT[64][72];
    const int tid = threadIdx.x;
    const int tx = tid & 15, ty = tid >> 4;
    #pragma unroll
    for (int t = 0; t < 4; t++) {
        int lin = tid + t * 256;
        int r = lin >> 4, c4 = (lin & 15) * 4;
        *reinterpret_cast<float4*>(&KVs[r][c4]) =
            *reinterpret_cast<const float4*>(&KVb[(size_t)r * HDIM + c4]);
        float4 q4 = *reinterpret_cast<const float4*>(&Qb[(size_t)r * HW + p0 + c4]);
        *reinterpret_cast<float4*>(&Qs[r][c4]) = q4;
    }
    __syncthreads();
    float acc[4][4] = {};
    #pragma unroll 8
    for (int k = 0; k < 64; k++) {
        float4 q4 = *reinterpret_cast<const float4*>(&Qs[k][tx * 4]);
        float4 a4 = *reinterpret_cast<const float4*>(&KVs[k][ty * 4]);
        float ra[4] = {a4.x, a4.y, a4.z, a4.w};
        float rb[4] = {q4.x, q4.y, q4.z, q4.w};
        #pragma unroll
        for (int i = 0; i < 4; i++)
            #pragma unroll
            for (int j = 0; j < 4; j++)
                acc[i][j] = fmaf(ra[i], rb[j], acc[i][j]);
    }
    const int bq = b * HW + p0 + tx * 4;
    float inv[4];
    #pragma unroll
    for (int j = 0; j < 4; j++) inv[j] = 1.f / qsum[bq + j];
    #pragma unroll
    for (int i = 0; i < 4; i++)
        #pragma unroll
        for (int j = 0; j < 4; j++) {
            __half hv = __float2half_rn(acc[i][j] * inv[j]);
            TT[tx * 4 + j][ty * 4 + i] = *reinterpret_cast<unsigned short*>(&hv);
        }
    __syncthreads();
    #pragma unroll
    for (int t = 0; t < 2; t++) {
        int cc = tid + t * 256;
        int p = cc >> 3, co = (cc & 7) * 8;
        uint4 v = *reinterpret_cast<const uint4*>(&TT[p][co]);
        size_t o = ((size_t)b * HW + p0 + p) * CCH + h * 64 + co;
        *reinterpret_cast<uint4*>(Th + o) = v;
    }
}

// ================= launch =================
extern "C" void kernel_launch(void* const* d_in, const int* in_sizes, int n_in,
                              void* d_out, int out_size) {
    const float* x     = (const float*)d_in[0];
    const float* ln1w  = (const float*)d_in[1];
    const float* ln1b  = (const float*)d_in[2];
    const float* qw    = (const float*)d_in[3];
    const float* qb    = (const float*)d_in[4];
    const float* kw    = (const float*)d_in[5];
    const float* kb    = (const float*)d_in[6];
    const float* vw    = (const float*)d_in[7];
    const float* vb    = (const float*)d_in[8];
    const float* huw   = (const float*)d_in[9];
    const float* hub   = (const float*)d_in[10];
    const float* ln2w  = (const float*)d_in[11];
    const float* ln2b  = (const float*)d_in[12];
    const float* ff1w  = (const float*)d_in[13];
    const float* ff1b  = (const float*)d_in[14];
    const float* ff2w  = (const float*)d_in[15];
    const float* ff2b  = (const float*)d_in[16];
    float* out = (float*)d_out;

    float *QKV, *R, *KVp, *KV, *qsum, *kinv, *bqkv;
    float2 *part, *stats;
    __half *Th, *Fh, *Wh;
    cudaGetSymbolAddress((void**)&QKV, g_QKV);
    cudaGetSymbolAddress((void**)&R, g_R);
    cudaGetSymbolAddress((void**)&KVp, g_KVp);
    cudaGetSymbolAddress((void**)&KV, g_KV);
    cudaGetSymbolAddress((void**)&qsum, g_qsum);
    cudaGetSymbolAddress((void**)&kinv, g_kinv);
    cudaGetSymbolAddress((void**)&bqkv, g_bqkv);
    cudaGetSymbolAddress((void**)&part, g_part);
    cudaGetSymbolAddress((void**)&stats, g_stats);
    cudaGetSymbolAddress((void**)&Th, g_Th);
    cudaGetSymbolAddress((void**)&Fh, g_Fh);
    cudaGetSymbolAddress((void**)&Wh, g_Wh);

    const int SMEM = 4 * GSTAGE;   // 81920
    cudaFuncSetAttribute(hmma_gemm<1>, cudaFuncAttributeMaxDynamicSharedMemorySize, SMEM);
    cudaFuncSetAttribute(hmma_gemm<2>, cudaFuncAttributeMaxDynamicSharedMemorySize, SMEM);
    cudaFuncSetAttribute(hmma_gemm<3>, cudaFuncAttributeMaxDynamicSharedMemorySize, SMEM);
    cudaFuncSetAttribute(hmma_gemm<5>, cudaFuncAttributeMaxDynamicSharedMemorySize, SMEM);

    const dim3 gT(HW / 32, CCH / 32, BATCH);         // (128, 16, 16)
    const dim3 gQKVg(HW / 128, 1536 / 128, BATCH);   // (32, 12, 16)
    const dim3 gG512(HW / 128, CCH / 128, BATCH);    // (32, 4, 16)
    const dim3 gG2048(HW / 128, DHID / 128, BATCH);  // (32, 16, 16)

    // weight conversion + bias pack
    wconv_all<<<WTOT / 256, 256>>>(qw, kw, vw, huw, ff1w, ff2w, Wh);
    pack_bias<<<2, 768>>>(qb, kb, vb, bqkv);

    // ln1 -> Th
    ln_stats<<<dim3(128, BATCH), 256>>>(x, part);
    ln_finalize<<<BATCH, 128>>>(part, stats);
    conv_t<1, 0><<<gT, 256>>>(x, ln1w, ln1b, stats, Th, nullptr);

    // fused QKV GEMM
    hmma_gemm<5><<<gQKVg, 256, SMEM>>>(Wh, Th, bqkv, nullptr, QKV, nullptr, nullptr, CCH, 1536);

    colsum<<<(BATCH * HW) / 256, 256>>>(QKV, qsum);
    rowsum_inv<<<BATCH * CCH, 256>>>(QKV, kinv);

    kv_part<<<dim3(8, 128), 256>>>(QKV, KVp);
    kv_reduce<<<128, 256>>>(KVp, kinv, KV);
    attn_kernel<<<dim3(HW / 64, BATCH * NHEAD), 256>>>(KV, QKV, qsum, Th);

    // R = x + hu(attn); LN2 partials fused
    hmma_gemm<1><<<gG512, 256, SMEM>>>(Wh + WOFF_HU, Th, hub, x, R, nullptr, part, CCH, CCH);
    ln_finalize<<<BATCH, 128>>>(part, stats);

    // ln2 fused: out (fp32) + Th (fp16 pixel-major)
    conv_t<1, 1><<<gT, 256>>>(R, ln2w, ln2b, stats, Th, out);

    // Fh = fp16(gelu(ff1)); out += ff2(Fh)
    hmma_gemm<2><<<gG2048, 256, SMEM>>>(Wh + WOFF_FF1, Th, ff1b, nullptr, nullptr, Fh, nullptr, CCH, DHID);
    hmma_gemm<3><<<gG512, 256, SMEM>>>(Wh + WOFF_FF2, Fh, ff2b, nullptr, out, nullptr, nullptr, DHID, CCH);
}